// round 1
// baseline (speedup 1.0000x reference)
#include <cuda_runtime.h>
#include <math.h>

#define SEQ     2048
#define DMODEL  1024
#define NH      16
#define DHEAD   64
#define FF      4096
#define MTOK    8192   // B*S
#define NBATCH  4

// ---------------- scratch (static device globals; no allocations) ----------------
__device__ float g_qkv[3u * MTOK * DMODEL];   // q | k | v, each [BH][S][DH]
__device__ float g_attn[MTOK * DMODEL];       // attention out, [B,S,H*DH]
__device__ float g_tmp [MTOK * DMODEL];       // pre-LN sums
__device__ float g_y   [MTOK * DMODEL];       // LN1 output (kept for residual 2)
__device__ float g_ff  [MTOK * FF];           // FFN hidden

// =================================================================================
// Generic SGEMM: C[M,N] = A[M,K] * B[K,N] + bias[N] (+ resid[M,N]) (relu)
// BM=128, BN=64, BK=16, 128 threads, 8x8 micro-tile per thread.
// =================================================================================
template<bool RELU, bool RESID>
__global__ void __launch_bounds__(128) sgemm_kernel(
    const float* __restrict__ A, const float* __restrict__ B,
    const float* __restrict__ bias, const float* __restrict__ resid,
    float* __restrict__ C, int M, int N, int K)
{
    __shared__ __align__(16) float As[16][132];   // [k][m], padded
    __shared__ __align__(16) float Bs[16][68];    // [k][n], padded

    const int t  = threadIdx.x;
    const int tx = t & 7;          // 0..7  -> 8 cols of 8
    const int ty = t >> 3;         // 0..15 -> 16 rows of 8
    const int m0 = blockIdx.x * 128;
    const int n0 = blockIdx.y * 64;

    float acc[8][8];
#pragma unroll
    for (int i = 0; i < 8; i++)
#pragma unroll
        for (int j = 0; j < 8; j++) acc[i][j] = 0.f;

    const int ar  = t >> 2;          // 0..31  A row group
    const int akq = (t & 3) * 4;     // 0,4,8,12 within BK
    const int bc  = (t & 15) * 4;    // 0..60 B col
    const int br  = t >> 4;          // 0..7  B row group

    for (int k0 = 0; k0 < K; k0 += 16) {
        // A tile -> As transposed
#pragma unroll
        for (int i = 0; i < 4; i++) {
            const int row = ar + 32 * i;
            const float4 v = *(const float4*)(A + (size_t)(m0 + row) * K + k0 + akq);
            As[akq + 0][row] = v.x;
            As[akq + 1][row] = v.y;
            As[akq + 2][row] = v.z;
            As[akq + 3][row] = v.w;
        }
        // B tile -> Bs
#pragma unroll
        for (int i = 0; i < 2; i++) {
            const int row = br + 8 * i;
            const float4 v = *(const float4*)(B + (size_t)(k0 + row) * N + n0 + bc);
            *(float4*)&Bs[row][bc] = v;
        }
        __syncthreads();

#pragma unroll
        for (int kk = 0; kk < 16; kk++) {
            float a[8], b[8];
            *(float4*)(a)     = *(float4*)&As[kk][ty * 8];
            *(float4*)(a + 4) = *(float4*)&As[kk][ty * 8 + 4];
            *(float4*)(b)     = *(float4*)&Bs[kk][tx * 8];
            *(float4*)(b + 4) = *(float4*)&Bs[kk][tx * 8 + 4];
#pragma unroll
            for (int i = 0; i < 8; i++)
#pragma unroll
                for (int j = 0; j < 8; j++)
                    acc[i][j] = fmaf(a[i], b[j], acc[i][j]);
        }
        __syncthreads();
    }

    // epilogue
#pragma unroll
    for (int i = 0; i < 8; i++) {
        const int m = m0 + ty * 8 + i;
#pragma unroll
        for (int j = 0; j < 8; j += 4) {
            const int n = n0 + tx * 8 + j;
            float4 r;
            r.x = acc[i][j]     + bias[n];
            r.y = acc[i][j + 1] + bias[n + 1];
            r.z = acc[i][j + 2] + bias[n + 2];
            r.w = acc[i][j + 3] + bias[n + 3];
            if (RESID) {
                const float4 rv = *(const float4*)(resid + (size_t)m * N + n);
                r.x += rv.x; r.y += rv.y; r.z += rv.z; r.w += rv.w;
            }
            if (RELU) {
                r.x = fmaxf(r.x, 0.f); r.y = fmaxf(r.y, 0.f);
                r.z = fmaxf(r.z, 0.f); r.w = fmaxf(r.w, 0.f);
            }
            *(float4*)(C + (size_t)m * N + n) = r;
        }
    }
}

// =================================================================================
// QKV GEMM: z in {0,1,2} selects (wq,bq,q) / (wk,bk,k) / (wv,bv,v).
// N-tile (64) == exactly one head, so weight slice is row-major [D, 64].
// Output layout: [BH][S][DH].
// =================================================================================
__global__ void __launch_bounds__(128) qkv_kernel(
    const float* __restrict__ x,
    const float* __restrict__ wq, const float* __restrict__ wk, const float* __restrict__ wv,
    const float* __restrict__ bq, const float* __restrict__ bk, const float* __restrict__ bv)
{
    __shared__ __align__(16) float As[16][132];
    __shared__ __align__(16) float Bs[16][68];

    const int z = blockIdx.z;
    const float* W    = (z == 0) ? wq : ((z == 1) ? wk : wv);
    const float* bias = (z == 0) ? bq : ((z == 1) ? bk : bv);
    float* out = g_qkv + (size_t)z * MTOK * DMODEL;

    const int h = blockIdx.y;
    W    += (size_t)h * DMODEL * DHEAD;
    bias += h * DHEAD;

    const int t  = threadIdx.x;
    const int tx = t & 7;
    const int ty = t >> 3;
    const int m0 = blockIdx.x * 128;

    float acc[8][8];
#pragma unroll
    for (int i = 0; i < 8; i++)
#pragma unroll
        for (int j = 0; j < 8; j++) acc[i][j] = 0.f;

    const int ar  = t >> 2;
    const int akq = (t & 3) * 4;
    const int bc  = (t & 15) * 4;
    const int br  = t >> 4;

    for (int k0 = 0; k0 < DMODEL; k0 += 16) {
#pragma unroll
        for (int i = 0; i < 4; i++) {
            const int row = ar + 32 * i;
            const float4 v = *(const float4*)(x + (size_t)(m0 + row) * DMODEL + k0 + akq);
            As[akq + 0][row] = v.x;
            As[akq + 1][row] = v.y;
            As[akq + 2][row] = v.z;
            As[akq + 3][row] = v.w;
        }
#pragma unroll
        for (int i = 0; i < 2; i++) {
            const int row = br + 8 * i;
            const float4 v = *(const float4*)(W + (size_t)(k0 + row) * DHEAD + bc);
            *(float4*)&Bs[row][bc] = v;
        }
        __syncthreads();

#pragma unroll
        for (int kk = 0; kk < 16; kk++) {
            float a[8], b[8];
            *(float4*)(a)     = *(float4*)&As[kk][ty * 8];
            *(float4*)(a + 4) = *(float4*)&As[kk][ty * 8 + 4];
            *(float4*)(b)     = *(float4*)&Bs[kk][tx * 8];
            *(float4*)(b + 4) = *(float4*)&Bs[kk][tx * 8 + 4];
#pragma unroll
            for (int i = 0; i < 8; i++)
#pragma unroll
                for (int j = 0; j < 8; j++)
                    acc[i][j] = fmaf(a[i], b[j], acc[i][j]);
        }
        __syncthreads();
    }

    // epilogue -> out[((b*NH + h)*SEQ + s)*DHEAD + e]
#pragma unroll
    for (int i = 0; i < 8; i++) {
        const int m = m0 + ty * 8 + i;
        const int b = m >> 11;          // / SEQ
        const int s = m & 2047;         // % SEQ
        float* dst = out + ((size_t)(b * NH + h) * SEQ + s) * DHEAD;
#pragma unroll
        for (int j = 0; j < 8; j += 4) {
            const int e = tx * 8 + j;
            float4 r;
            r.x = acc[i][j]     + bias[e];
            r.y = acc[i][j + 1] + bias[e + 1];
            r.z = acc[i][j + 2] + bias[e + 2];
            r.w = acc[i][j + 3] + bias[e + 3];
            *(float4*)(dst + e) = r;
        }
    }
}

// =================================================================================
// Fused attention (flash style). Per CTA: one (b,h), 64 query rows.
// Stream 64-key tiles: S = Q*K^T (smem, Q/K stored [e][row]), online softmax,
// P staged via smem [kv][qr], O += P*V. 128 threads: ty(16) x tx(8), micro 4x8.
// =================================================================================
#define ATT_ROWPAD 68
#define ATT_SMEM_BYTES ((ATT_ROWPAD * 64 * 3 + 64 * 64) * 4)

__global__ void __launch_bounds__(128) attn_kernel(
    const float* __restrict__ qbuf, const float* __restrict__ kbuf,
    const float* __restrict__ vbuf, float* __restrict__ obuf)
{
    extern __shared__ __align__(16) float sm[];
    float* Qs = sm;                         // [e][r]  (64 x 68)
    float* Ks = Qs + 64 * ATT_ROWPAD;       // [e][r]
    float* Ps = Ks + 64 * ATT_ROWPAD;       // [kv][qr]
    float* Vs = Ps + 64 * ATT_ROWPAD;       // [kv][e] (64 x 64)

    const int t  = threadIdx.x;
    const int tx = t & 7;   // kv-col octet
    const int ty = t >> 3;  // q-row group
    const int bh = blockIdx.y;
    const int q0 = blockIdx.x * 64;

    const float* Q  = qbuf + ((size_t)bh * SEQ + q0) * DHEAD;
    const float* Kp = kbuf + (size_t)bh * SEQ * DHEAD;
    const float* Vp = vbuf + (size_t)bh * SEQ * DHEAD;

    const int lr = t >> 1;            // 0..63 row
    const int le = (t & 1) * 32;      // half of 64 dims

    // load Q (scaled by 1/sqrt(DH)), transposed [e][r]
#pragma unroll
    for (int v = 0; v < 8; v++) {
        const float4 q4 = *(const float4*)(Q + (size_t)lr * DHEAD + le + v * 4);
        const int e = le + v * 4;
        Qs[(e + 0) * ATT_ROWPAD + lr] = q4.x * 0.125f;
        Qs[(e + 1) * ATT_ROWPAD + lr] = q4.y * 0.125f;
        Qs[(e + 2) * ATT_ROWPAD + lr] = q4.z * 0.125f;
        Qs[(e + 3) * ATT_ROWPAD + lr] = q4.w * 0.125f;
    }

    float m_i[4], l_i[4], o[4][8];
#pragma unroll
    for (int i = 0; i < 4; i++) {
        m_i[i] = -INFINITY; l_i[i] = 0.f;
#pragma unroll
        for (int j = 0; j < 8; j++) o[i][j] = 0.f;
    }

    for (int kt = 0; kt < SEQ / 64; kt++) {
        // load K (transposed) and V (natural)
        const float* Kr = Kp + ((size_t)(kt * 64 + lr)) * DHEAD + le;
        const float* Vr = Vp + ((size_t)(kt * 64 + lr)) * DHEAD + le;
#pragma unroll
        for (int v = 0; v < 8; v++) {
            const float4 k4 = *(const float4*)(Kr + v * 4);
            const int e = le + v * 4;
            Ks[(e + 0) * ATT_ROWPAD + lr] = k4.x;
            Ks[(e + 1) * ATT_ROWPAD + lr] = k4.y;
            Ks[(e + 2) * ATT_ROWPAD + lr] = k4.z;
            Ks[(e + 3) * ATT_ROWPAD + lr] = k4.w;
            *(float4*)&Vs[lr * 64 + e] = *(const float4*)(Vr + v * 4);
        }
        __syncthreads();

        // S = Q * K^T  (micro 4x8)
        float s[4][8];
#pragma unroll
        for (int i = 0; i < 4; i++)
#pragma unroll
            for (int j = 0; j < 8; j++) s[i][j] = 0.f;

#pragma unroll 8
        for (int e = 0; e < 64; e++) {
            float a[4], b[8];
            *(float4*)(a)     = *(float4*)&Qs[e * ATT_ROWPAD + ty * 4];
            *(float4*)(b)     = *(float4*)&Ks[e * ATT_ROWPAD + tx * 8];
            *(float4*)(b + 4) = *(float4*)&Ks[e * ATT_ROWPAD + tx * 8 + 4];
#pragma unroll
            for (int i = 0; i < 4; i++)
#pragma unroll
                for (int j = 0; j < 8; j++)
                    s[i][j] = fmaf(a[i], b[j], s[i][j]);
        }

        // online softmax update; write P to smem
#pragma unroll
        for (int i = 0; i < 4; i++) {
            float tm = s[i][0];
#pragma unroll
            for (int j = 1; j < 8; j++) tm = fmaxf(tm, s[i][j]);
            tm = fmaxf(tm, __shfl_xor_sync(0xffffffffu, tm, 1));
            tm = fmaxf(tm, __shfl_xor_sync(0xffffffffu, tm, 2));
            tm = fmaxf(tm, __shfl_xor_sync(0xffffffffu, tm, 4));

            const float mn    = fmaxf(m_i[i], tm);
            const float alpha = __expf(m_i[i] - mn);
            float rs = 0.f;
#pragma unroll
            for (int j = 0; j < 8; j++) {
                s[i][j] = __expf(s[i][j] - mn);
                rs += s[i][j];
            }
            rs += __shfl_xor_sync(0xffffffffu, rs, 1);
            rs += __shfl_xor_sync(0xffffffffu, rs, 2);
            rs += __shfl_xor_sync(0xffffffffu, rs, 4);

            l_i[i] = l_i[i] * alpha + rs;
            m_i[i] = mn;
#pragma unroll
            for (int j = 0; j < 8; j++) o[i][j] *= alpha;
#pragma unroll
            for (int j = 0; j < 8; j++)
                Ps[(tx * 8 + j) * ATT_ROWPAD + ty * 4 + i] = s[i][j];
        }
        __syncthreads();

        // O += P * V
#pragma unroll 8
        for (int kv = 0; kv < 64; kv++) {
            float a[4], b[8];
            *(float4*)(a)     = *(float4*)&Ps[kv * ATT_ROWPAD + ty * 4];
            *(float4*)(b)     = *(float4*)&Vs[kv * 64 + tx * 8];
            *(float4*)(b + 4) = *(float4*)&Vs[kv * 64 + tx * 8 + 4];
#pragma unroll
            for (int i = 0; i < 4; i++)
#pragma unroll
                for (int j = 0; j < 8; j++)
                    o[i][j] = fmaf(a[i], b[j], o[i][j]);
        }
        __syncthreads();
    }

    // epilogue: write [B,S,H*DH]
    const int b = bh >> 4;
    const int h = bh & 15;
#pragma unroll
    for (int i = 0; i < 4; i++) {
        const int srow = q0 + ty * 4 + i;
        const float inv = 1.f / l_i[i];
        float* dst = obuf + ((size_t)(b * SEQ + srow) * NH + h) * DHEAD + tx * 8;
        float4 r0, r1;
        r0.x = o[i][0] * inv; r0.y = o[i][1] * inv; r0.z = o[i][2] * inv; r0.w = o[i][3] * inv;
        r1.x = o[i][4] * inv; r1.y = o[i][5] * inv; r1.z = o[i][6] * inv; r1.w = o[i][7] * inv;
        *(float4*)(dst)     = r0;
        *(float4*)(dst + 4) = r1;
    }
}

// =================================================================================
// LayerNorm over D=1024. One CTA (256 thr) per row, float4 per thread.
// =================================================================================
__global__ void __launch_bounds__(256) ln_kernel(
    const float* __restrict__ in, const float* __restrict__ g,
    const float* __restrict__ b, float* __restrict__ out)
{
    const int row = blockIdx.x;
    const int tid = threadIdx.x;
    const float4 v = ((const float4*)(in + (size_t)row * DMODEL))[tid];

    float s  = v.x + v.y + v.z + v.w;
    float sq = v.x * v.x + v.y * v.y + v.z * v.z + v.w * v.w;
#pragma unroll
    for (int off = 16; off > 0; off >>= 1) {
        s  += __shfl_xor_sync(0xffffffffu, s,  off);
        sq += __shfl_xor_sync(0xffffffffu, sq, off);
    }
    __shared__ float ss[8], ssq[8];
    if ((tid & 31) == 0) { ss[tid >> 5] = s; ssq[tid >> 5] = sq; }
    __syncthreads();
    s = 0.f; sq = 0.f;
#pragma unroll
    for (int i = 0; i < 8; i++) { s += ss[i]; sq += ssq[i]; }

    const float mu   = s * (1.f / DMODEL);
    const float var  = sq * (1.f / DMODEL) - mu * mu;
    const float rstd = rsqrtf(var + 1e-5f);

    const float4 gg = ((const float4*)g)[tid];
    const float4 bb = ((const float4*)b)[tid];
    float4 r;
    r.x = (v.x - mu) * rstd * gg.x + bb.x;
    r.y = (v.y - mu) * rstd * gg.y + bb.y;
    r.z = (v.z - mu) * rstd * gg.z + bb.z;
    r.w = (v.w - mu) * rstd * gg.w + bb.w;
    ((float4*)(out + (size_t)row * DMODEL))[tid] = r;
}

// =================================================================================
// Host launcher
// =================================================================================
extern "C" void kernel_launch(void* const* d_in, const int* in_sizes, int n_in,
                              void* d_out, int out_size)
{
    (void)in_sizes; (void)n_in; (void)out_size;
    const float* x     = (const float*)d_in[0];
    const float* wq    = (const float*)d_in[1];
    const float* bq    = (const float*)d_in[2];
    const float* wk    = (const float*)d_in[3];
    const float* bk    = (const float*)d_in[4];
    const float* wv    = (const float*)d_in[5];
    const float* bv    = (const float*)d_in[6];
    const float* wo    = (const float*)d_in[7];
    const float* bo    = (const float*)d_in[8];
    const float* ln1_g = (const float*)d_in[9];
    const float* ln1_b = (const float*)d_in[10];
    const float* w1    = (const float*)d_in[11];
    const float* b1    = (const float*)d_in[12];
    const float* w2    = (const float*)d_in[13];
    const float* b2    = (const float*)d_in[14];
    const float* ln2_g = (const float*)d_in[15];
    const float* ln2_b = (const float*)d_in[16];
    float* out = (float*)d_out;

    static float *p_qkv = nullptr, *p_attn = nullptr, *p_tmp = nullptr,
                 *p_y = nullptr, *p_ff = nullptr;
    if (!p_qkv) {
        cudaGetSymbolAddress((void**)&p_qkv,  g_qkv);
        cudaGetSymbolAddress((void**)&p_attn, g_attn);
        cudaGetSymbolAddress((void**)&p_tmp,  g_tmp);
        cudaGetSymbolAddress((void**)&p_y,    g_y);
        cudaGetSymbolAddress((void**)&p_ff,   g_ff);
        cudaFuncSetAttribute(attn_kernel,
                             cudaFuncAttributeMaxDynamicSharedMemorySize,
                             ATT_SMEM_BYTES);
    }

    const size_t QK = (size_t)MTOK * DMODEL;

    // 1) QKV projections
    qkv_kernel<<<dim3(MTOK / 128, NH, 3), 128>>>(x, wq, wk, wv, bq, bk, bv);

    // 2) fused attention
    attn_kernel<<<dim3(SEQ / 64, NBATCH * NH), 128, ATT_SMEM_BYTES>>>(
        p_qkv, p_qkv + QK, p_qkv + 2 * QK, p_attn);

    // 3) output projection + bias + residual(x)
    sgemm_kernel<false, true><<<dim3(MTOK / 128, DMODEL / 64), 128>>>(
        p_attn, wo, bo, x, p_tmp, MTOK, DMODEL, DMODEL);

    // 4) LN1 -> y
    ln_kernel<<<MTOK, 256>>>(p_tmp, ln1_g, ln1_b, p_y);

    // 5) FFN1: relu(y*w1 + b1)
    sgemm_kernel<true, false><<<dim3(MTOK / 128, FF / 64), 128>>>(
        p_y, w1, b1, nullptr, p_ff, MTOK, FF, DMODEL);

    // 6) FFN2: ff*w2 + b2 + residual(y)
    sgemm_kernel<false, true><<<dim3(MTOK / 128, DMODEL / 64), 128>>>(
        p_ff, w2, b2, p_y, p_tmp, MTOK, DMODEL, FF);

    // 7) LN2 -> out
    ln_kernel<<<MTOK, 256>>>(p_tmp, ln2_g, ln2_b, out);
}

// round 5
// speedup vs baseline: 1.6392x; 1.6392x over previous
#include <cuda_runtime.h>
#include <math.h>
#include <stdint.h>

#define SEQ     2048
#define DMODEL  1024
#define NH      16
#define DHEAD   64
#define FF      4096
#define MTOK    8192   // B*S
#define NBATCH  4
#define QKVLD   3072   // q|k|v concatenated row stride

// ---------------- scratch (static device globals; no allocations) ----------------
__device__ float g_qkv [(size_t)MTOK * QKVLD];    // [B,S, q(1024)|k(1024)|v(1024)]
__device__ float g_attn[(size_t)MTOK * DMODEL];   // attention out, [B,S,H*DH]
__device__ float g_tmp [(size_t)MTOK * DMODEL];   // pre-LN sums
__device__ float g_y   [(size_t)MTOK * DMODEL];   // LN1 output
__device__ float g_ff  [(size_t)MTOK * FF];       // FFN hidden
__device__ float g_wqkvT[(size_t)QKVLD * DMODEL]; // [3072,1024] = (wq|wk|wv)^T per head
__device__ float g_woT [(size_t)DMODEL * DMODEL]; // [1024,1024]
__device__ float g_w1T [(size_t)FF * DMODEL];     // [4096,1024]
__device__ float g_w2T [(size_t)DMODEL * FF];     // [1024,4096]
__device__ float g_bqkv[QKVLD];

// ======================= helpers =======================
__device__ __forceinline__ uint32_t smem_u32(const void* p) {
    uint32_t a;
    asm("{ .reg .u64 t; cvta.to.shared.u64 t, %1; cvt.u32.u64 %0, t; }" : "=r"(a) : "l"(p));
    return a;
}
__device__ __forceinline__ void cp16(uint32_t dst, const void* src) {
    asm volatile("cp.async.cg.shared.global [%0], [%1], 16;" :: "r"(dst), "l"(src));
}
__device__ __forceinline__ uint32_t f2tf32(float f) {
    uint32_t r;
    asm("cvt.rna.tf32.f32 %0, %1;" : "=r"(r) : "f"(f));
    return r;
}
__device__ __forceinline__ void mma_tf32(float* d, const uint32_t* a, const uint32_t* b) {
    asm volatile("mma.sync.aligned.m16n8k8.row.col.f32.tf32.tf32.f32 "
                 "{%0,%1,%2,%3}, {%4,%5,%6,%7}, {%8,%9}, {%0,%1,%2,%3};"
                 : "+f"(d[0]), "+f"(d[1]), "+f"(d[2]), "+f"(d[3])
                 : "r"(a[0]), "r"(a[1]), "r"(a[2]), "r"(a[3]), "r"(b[0]), "r"(b[1]));
}

// smem: As[2][128][36] | Bs[2][128][36] floats
#define GM_LDK   36
#define GM_BUF   (128 * GM_LDK)                 // floats per buffer
#define GM_SMEM_BYTES (4 * GM_BUF * 4)          // 73728

// =================================================================================
// TF32 mma.sync GEMM: C[M,N] = A[M,K] * Bt[N,K]^T + bias[N] (+resid) (relu)
// CTA 128x128, BK=32, 256 threads, warp tile 64x32 (2 m-warps x 4 n-warps).
// =================================================================================
template<bool RELU, bool RESID>
__global__ void __launch_bounds__(256, 2) mma_gemm(
    const float* __restrict__ A, const float* __restrict__ Bt,
    const float* __restrict__ bias, const float* __restrict__ resid,
    float* __restrict__ C, int M, int N, int K)
{
    extern __shared__ __align__(16) float smf[];
    const uint32_t sb = smem_u32(smf);
    const int t    = threadIdx.x;
    const int lane = t & 31;
    const int w    = t >> 5;
    const int wm   = w & 1;          // 0..1 -> 64-row strip
    const int wn   = w >> 1;         // 0..3 -> 32-col strip
    const int qr   = lane >> 2;      // 0..7
    const int qc   = lane & 3;       // 0..3
    const int m0   = blockIdx.x * 128;
    const int n0   = blockIdx.y * 128;

    float acc[4][4][4];
#pragma unroll
    for (int mi = 0; mi < 4; mi++)
#pragma unroll
        for (int ni = 0; ni < 4; ni++)
#pragma unroll
            for (int k = 0; k < 4; k++) acc[mi][ni][k] = 0.f;

    const int NC = K >> 5;

    auto load_chunk = [&](int c, int s) {
        const int k0 = c << 5;
        const uint32_t aB = sb + (uint32_t)s * (GM_BUF * 4);
        const uint32_t bB = sb + (uint32_t)(2 * GM_BUF * 4) + (uint32_t)s * (GM_BUF * 4);
#pragma unroll
        for (int i = 0; i < 4; i++) {
            const int id = t + 256 * i;
            const int r = id >> 3, sg = id & 7;
            cp16(aB + (uint32_t)(r * (GM_LDK * 4) + sg * 16),
                 A + (size_t)(m0 + r) * K + k0 + sg * 4);
        }
#pragma unroll
        for (int i = 0; i < 4; i++) {
            const int id = t + 256 * i;
            const int r = id >> 3, sg = id & 7;
            cp16(bB + (uint32_t)(r * (GM_LDK * 4) + sg * 16),
                 Bt + (size_t)(n0 + r) * K + k0 + sg * 4);
        }
        asm volatile("cp.async.commit_group;" ::: "memory");
    };

    load_chunk(0, 0);

    for (int c = 0; c < NC; ++c) {
        if (c + 1 < NC) {
            load_chunk(c + 1, (c + 1) & 1);
            asm volatile("cp.async.wait_group 1;" ::: "memory");
        } else {
            asm volatile("cp.async.wait_group 0;" ::: "memory");
        }
        __syncthreads();

        const int buf = c & 1;
        const float* Asf = smf + buf * GM_BUF;
        const float* Bsf = smf + 2 * GM_BUF + buf * GM_BUF;

#pragma unroll
        for (int kk = 0; kk < 4; kk++) {
            const int k0 = kk * 8;
            uint32_t af[4][4], bf[4][2];
#pragma unroll
            for (int mi = 0; mi < 4; mi++) {
                const float* p = Asf + (wm * 64 + mi * 16 + qr) * GM_LDK + k0 + qc;
                af[mi][0] = f2tf32(p[0]);
                af[mi][2] = f2tf32(p[4]);
                af[mi][1] = f2tf32(p[8 * GM_LDK]);
                af[mi][3] = f2tf32(p[8 * GM_LDK + 4]);
            }
#pragma unroll
            for (int ni = 0; ni < 4; ni++) {
                const float* p = Bsf + (wn * 32 + ni * 8 + qr) * GM_LDK + k0 + qc;
                bf[ni][0] = f2tf32(p[0]);
                bf[ni][1] = f2tf32(p[4]);
            }
#pragma unroll
            for (int mi = 0; mi < 4; mi++)
#pragma unroll
                for (int ni = 0; ni < 4; ni++)
                    mma_tf32(acc[mi][ni], af[mi], bf[ni]);
        }
        __syncthreads();
    }

    // epilogue
#pragma unroll
    for (int mi = 0; mi < 4; mi++) {
        const int r0 = m0 + wm * 64 + mi * 16 + qr;
        const int r1 = r0 + 8;
#pragma unroll
        for (int ni = 0; ni < 4; ni++) {
            const int nb = n0 + wn * 32 + ni * 8 + qc * 2;
            const float b0 = bias[nb], b1 = bias[nb + 1];
            float2 v0, v1;
            v0.x = acc[mi][ni][0] + b0; v0.y = acc[mi][ni][1] + b1;
            v1.x = acc[mi][ni][2] + b0; v1.y = acc[mi][ni][3] + b1;
            if (RESID) {
                const float2 q0 = *(const float2*)(resid + (size_t)r0 * N + nb);
                const float2 q1 = *(const float2*)(resid + (size_t)r1 * N + nb);
                v0.x += q0.x; v0.y += q0.y; v1.x += q1.x; v1.y += q1.y;
            }
            if (RELU) {
                v0.x = fmaxf(v0.x, 0.f); v0.y = fmaxf(v0.y, 0.f);
                v1.x = fmaxf(v1.x, 0.f); v1.y = fmaxf(v1.y, 0.f);
            }
            *(float2*)(C + (size_t)r0 * N + nb) = v0;
            *(float2*)(C + (size_t)r1 * N + nb) = v1;
        }
    }
}

// =================================================================================
// Transposes + bias concat
// =================================================================================
__global__ void transpose_kernel(const float* __restrict__ in, float* __restrict__ out,
                                 int R, int C)
{
    __shared__ float tile[32][33];
    const int c0 = blockIdx.x * 32, r0 = blockIdx.y * 32;
#pragma unroll
    for (int i = 0; i < 4; i++)
        tile[threadIdx.y + 8 * i][threadIdx.x] =
            in[(size_t)(r0 + threadIdx.y + 8 * i) * C + c0 + threadIdx.x];
    __syncthreads();
#pragma unroll
    for (int i = 0; i < 4; i++)
        out[(size_t)(c0 + threadIdx.y + 8 * i) * R + r0 + threadIdx.x] =
            tile[threadIdx.x][threadIdx.y + 8 * i];
}

__global__ void qkvw_transpose_kernel(const float* __restrict__ wq,
                                      const float* __restrict__ wk,
                                      const float* __restrict__ wv,
                                      float* __restrict__ out)
{
    __shared__ float tile[32][33];
    const int zh = blockIdx.z;
    const int z = zh >> 4, h = zh & 15;
    const float* src = (z == 0 ? wq : (z == 1 ? wk : wv)) + (size_t)h * DMODEL * DHEAD; // [1024,64]
    float* dst = out + ((size_t)(z * 16 + h)) * DHEAD * DMODEL;                          // [64,1024]
    const int c0 = blockIdx.x * 32, r0 = blockIdx.y * 32;
#pragma unroll
    for (int i = 0; i < 4; i++)
        tile[threadIdx.y + 8 * i][threadIdx.x] =
            src[(size_t)(r0 + threadIdx.y + 8 * i) * DHEAD + c0 + threadIdx.x];
    __syncthreads();
#pragma unroll
    for (int i = 0; i < 4; i++)
        dst[(size_t)(c0 + threadIdx.y + 8 * i) * DMODEL + r0 + threadIdx.x] =
            tile[threadIdx.x][threadIdx.y + 8 * i];
}

__global__ void biascat_kernel(const float* __restrict__ bq, const float* __restrict__ bk,
                               const float* __restrict__ bv, float* __restrict__ out)
{
    const int i = blockIdx.x * 256 + threadIdx.x;
    out[i] = (i < 1024) ? bq[i] : ((i < 2048) ? bk[i - 1024] : bv[i - 2048]);
}

// =================================================================================
// Fused attention (flash style, fp32 SIMT), reads strided q|k|v from g_qkv.
// =================================================================================
#define ATT_ROWPAD 68
#define ATT_SMEM_BYTES ((ATT_ROWPAD * 64 * 3 + 64 * 64) * 4)

__global__ void __launch_bounds__(128) attn_kernel(
    const float* __restrict__ qkv, float* __restrict__ obuf)
{
    extern __shared__ __align__(16) float sm[];
    float* Qs = sm;
    float* Ks = Qs + 64 * ATT_ROWPAD;
    float* Ps = Ks + 64 * ATT_ROWPAD;
    float* Vs = Ps + 64 * ATT_ROWPAD;

    const int t  = threadIdx.x;
    const int tx = t & 7;
    const int ty = t >> 3;
    const int bh = blockIdx.y;
    const int b  = bh >> 4, h = bh & 15;
    const int q0 = blockIdx.x * 64;

    const float* Q  = qkv + ((size_t)(b * SEQ + q0)) * QKVLD + h * 64;
    const float* Kp = qkv + (size_t)b * SEQ * QKVLD + 1024 + h * 64;
    const float* Vp = qkv + (size_t)b * SEQ * QKVLD + 2048 + h * 64;

    const int lr = t >> 1;
    const int le = (t & 1) * 32;

#pragma unroll
    for (int v = 0; v < 8; v++) {
        const float4 q4 = *(const float4*)(Q + (size_t)lr * QKVLD + le + v * 4);
        const int e = le + v * 4;
        Qs[(e + 0) * ATT_ROWPAD + lr] = q4.x * 0.125f;
        Qs[(e + 1) * ATT_ROWPAD + lr] = q4.y * 0.125f;
        Qs[(e + 2) * ATT_ROWPAD + lr] = q4.z * 0.125f;
        Qs[(e + 3) * ATT_ROWPAD + lr] = q4.w * 0.125f;
    }

    float m_i[4], l_i[4], o[4][8];
#pragma unroll
    for (int i = 0; i < 4; i++) {
        m_i[i] = -INFINITY; l_i[i] = 0.f;
#pragma unroll
        for (int j = 0; j < 8; j++) o[i][j] = 0.f;
    }

    for (int kt = 0; kt < SEQ / 64; kt++) {
        const float* Kr = Kp + ((size_t)(kt * 64 + lr)) * QKVLD + le;
        const float* Vr = Vp + ((size_t)(kt * 64 + lr)) * QKVLD + le;
#pragma unroll
        for (int v = 0; v < 8; v++) {
            const float4 k4 = *(const float4*)(Kr + v * 4);
            const int e = le + v * 4;
            Ks[(e + 0) * ATT_ROWPAD + lr] = k4.x;
            Ks[(e + 1) * ATT_ROWPAD + lr] = k4.y;
            Ks[(e + 2) * ATT_ROWPAD + lr] = k4.z;
            Ks[(e + 3) * ATT_ROWPAD + lr] = k4.w;
            *(float4*)&Vs[lr * 64 + e] = *(const float4*)(Vr + v * 4);
        }
        __syncthreads();

        float s[4][8];
#pragma unroll
        for (int i = 0; i < 4; i++)
#pragma unroll
            for (int j = 0; j < 8; j++) s[i][j] = 0.f;

#pragma unroll 8
        for (int e = 0; e < 64; e++) {
            float a[4], bb[8];
            *(float4*)(a)      = *(float4*)&Qs[e * ATT_ROWPAD + ty * 4];
            *(float4*)(bb)     = *(float4*)&Ks[e * ATT_ROWPAD + tx * 8];
            *(float4*)(bb + 4) = *(float4*)&Ks[e * ATT_ROWPAD + tx * 8 + 4];
#pragma unroll
            for (int i = 0; i < 4; i++)
#pragma unroll
                for (int j = 0; j < 8; j++)
                    s[i][j] = fmaf(a[i], bb[j], s[i][j]);
        }

#pragma unroll
        for (int i = 0; i < 4; i++) {
            float tm = s[i][0];
#pragma unroll
            for (int j = 1; j < 8; j++) tm = fmaxf(tm, s[i][j]);
            tm = fmaxf(tm, __shfl_xor_sync(0xffffffffu, tm, 1));
            tm = fmaxf(tm, __shfl_xor_sync(0xffffffffu, tm, 2));
            tm = fmaxf(tm, __shfl_xor_sync(0xffffffffu, tm, 4));

            const float mn    = fmaxf(m_i[i], tm);
            const float alpha = __expf(m_i[i] - mn);
            float rs = 0.f;
#pragma unroll
            for (int j = 0; j < 8; j++) {
                s[i][j] = __expf(s[i][j] - mn);
                rs += s[i][j];
            }
            rs += __shfl_xor_sync(0xffffffffu, rs, 1);
            rs += __shfl_xor_sync(0xffffffffu, rs, 2);
            rs += __shfl_xor_sync(0xffffffffu, rs, 4);

            l_i[i] = l_i[i] * alpha + rs;
            m_i[i] = mn;
#pragma unroll
            for (int j = 0; j < 8; j++) o[i][j] *= alpha;
#pragma unroll
            for (int j = 0; j < 8; j++)
                Ps[(tx * 8 + j) * ATT_ROWPAD + ty * 4 + i] = s[i][j];
        }
        __syncthreads();

#pragma unroll 8
        for (int kv = 0; kv < 64; kv++) {
            float a[4], bb[8];
            *(float4*)(a)      = *(float4*)&Ps[kv * ATT_ROWPAD + ty * 4];
            *(float4*)(bb)     = *(float4*)&Vs[kv * 64 + tx * 8];
            *(float4*)(bb + 4) = *(float4*)&Vs[kv * 64 + tx * 8 + 4];
#pragma unroll
            for (int i = 0; i < 4; i++)
#pragma unroll
                for (int j = 0; j < 8; j++)
                    o[i][j] = fmaf(a[i], bb[j], o[i][j]);
        }
        __syncthreads();
    }

#pragma unroll
    for (int i = 0; i < 4; i++) {
        const int srow = q0 + ty * 4 + i;
        const float inv = 1.f / l_i[i];
        float* dst = obuf + ((size_t)(b * SEQ + srow) * NH + h) * DHEAD + tx * 8;
        float4 r0, r1;
        r0.x = o[i][0] * inv; r0.y = o[i][1] * inv; r0.z = o[i][2] * inv; r0.w = o[i][3] * inv;
        r1.x = o[i][4] * inv; r1.y = o[i][5] * inv; r1.z = o[i][6] * inv; r1.w = o[i][7] * inv;
        *(float4*)(dst)     = r0;
        *(float4*)(dst + 4) = r1;
    }
}

// =================================================================================
// LayerNorm over D=1024
// =================================================================================
__global__ void __launch_bounds__(256) ln_kernel(
    const float* __restrict__ in, const float* __restrict__ g,
    const float* __restrict__ b, float* __restrict__ out)
{
    const int row = blockIdx.x;
    const int tid = threadIdx.x;
    const float4 v = ((const float4*)(in + (size_t)row * DMODEL))[tid];

    float s  = v.x + v.y + v.z + v.w;
    float sq = v.x * v.x + v.y * v.y + v.z * v.z + v.w * v.w;
#pragma unroll
    for (int off = 16; off > 0; off >>= 1) {
        s  += __shfl_xor_sync(0xffffffffu, s,  off);
        sq += __shfl_xor_sync(0xffffffffu, sq, off);
    }
    __shared__ float ss[8], ssq[8];
    if ((tid & 31) == 0) { ss[tid >> 5] = s; ssq[tid >> 5] = sq; }
    __syncthreads();
    s = 0.f; sq = 0.f;
#pragma unroll
    for (int i = 0; i < 8; i++) { s += ss[i]; sq += ssq[i]; }

    const float mu   = s * (1.f / DMODEL);
    const float var  = sq * (1.f / DMODEL) - mu * mu;
    const float rstd = rsqrtf(var + 1e-5f);

    const float4 gg = ((const float4*)g)[tid];
    const float4 bb = ((const float4*)b)[tid];
    float4 r;
    r.x = (v.x - mu) * rstd * gg.x + bb.x;
    r.y = (v.y - mu) * rstd * gg.y + bb.y;
    r.z = (v.z - mu) * rstd * gg.z + bb.z;
    r.w = (v.w - mu) * rstd * gg.w + bb.w;
    ((float4*)(out + (size_t)row * DMODEL))[tid] = r;
}

// =================================================================================
// Host launcher
// =================================================================================
extern "C" void kernel_launch(void* const* d_in, const int* in_sizes, int n_in,
                              void* d_out, int out_size)
{
    (void)in_sizes; (void)n_in; (void)out_size;
    const float* x     = (const float*)d_in[0];
    const float* wq    = (const float*)d_in[1];
    const float* bq    = (const float*)d_in[2];
    const float* wk    = (const float*)d_in[3];
    const float* bk    = (const float*)d_in[4];
    const float* wv    = (const float*)d_in[5];
    const float* bv    = (const float*)d_in[6];
    const float* wo    = (const float*)d_in[7];
    const float* bo    = (const float*)d_in[8];
    const float* ln1_g = (const float*)d_in[9];
    const float* ln1_b = (const float*)d_in[10];
    const float* w1    = (const float*)d_in[11];
    const float* b1    = (const float*)d_in[12];
    const float* w2    = (const float*)d_in[13];
    const float* b2    = (const float*)d_in[14];
    const float* ln2_g = (const float*)d_in[15];
    const float* ln2_b = (const float*)d_in[16];
    float* out = (float*)d_out;

    static float *p_qkv = nullptr, *p_attn = nullptr, *p_tmp = nullptr, *p_y = nullptr,
                 *p_ff = nullptr, *p_wqkvT = nullptr, *p_woT = nullptr, *p_w1T = nullptr,
                 *p_w2T = nullptr, *p_bqkv = nullptr;
    if (!p_qkv) {
        cudaGetSymbolAddress((void**)&p_qkv,   g_qkv);
        cudaGetSymbolAddress((void**)&p_attn,  g_attn);
        cudaGetSymbolAddress((void**)&p_tmp,   g_tmp);
        cudaGetSymbolAddress((void**)&p_y,     g_y);
        cudaGetSymbolAddress((void**)&p_ff,    g_ff);
        cudaGetSymbolAddress((void**)&p_wqkvT, g_wqkvT);
        cudaGetSymbolAddress((void**)&p_woT,   g_woT);
        cudaGetSymbolAddress((void**)&p_w1T,   g_w1T);
        cudaGetSymbolAddress((void**)&p_w2T,   g_w2T);
        cudaGetSymbolAddress((void**)&p_bqkv,  g_bqkv);
        cudaFuncSetAttribute(attn_kernel,
                             cudaFuncAttributeMaxDynamicSharedMemorySize, ATT_SMEM_BYTES);
        cudaFuncSetAttribute(mma_gemm<false, false>,
                             cudaFuncAttributeMaxDynamicSharedMemorySize, GM_SMEM_BYTES);
        cudaFuncSetAttribute(mma_gemm<false, true>,
                             cudaFuncAttributeMaxDynamicSharedMemorySize, GM_SMEM_BYTES);
        cudaFuncSetAttribute(mma_gemm<true, false>,
                             cudaFuncAttributeMaxDynamicSharedMemorySize, GM_SMEM_BYTES);
    }

    // 0) weight transposes (+ bias concat)
    qkvw_transpose_kernel<<<dim3(2, 32, 48), dim3(32, 8)>>>(wq, wk, wv, p_wqkvT);
    transpose_kernel<<<dim3(32, 32),  dim3(32, 8)>>>(wo, p_woT, DMODEL, DMODEL);
    transpose_kernel<<<dim3(128, 32), dim3(32, 8)>>>(w1, p_w1T, DMODEL, FF);
    transpose_kernel<<<dim3(32, 128), dim3(32, 8)>>>(w2, p_w2T, FF, DMODEL);
    biascat_kernel<<<12, 256>>>(bq, bk, bv, p_bqkv);

    // 1) fused QKV projection: [8192,1024] x [3072,1024]^T -> [8192,3072]
    mma_gemm<false, false><<<dim3(MTOK / 128, QKVLD / 128), 256, GM_SMEM_BYTES>>>(
        x, p_wqkvT, p_bqkv, nullptr, p_qkv, MTOK, QKVLD, DMODEL);

    // 2) fused attention (fp32 SIMT)
    attn_kernel<<<dim3(SEQ / 64, NBATCH * NH), 128, ATT_SMEM_BYTES>>>(p_qkv, p_attn);

    // 3) output projection + bias + residual(x)
    mma_gemm<false, true><<<dim3(MTOK / 128, DMODEL / 128), 256, GM_SMEM_BYTES>>>(
        p_attn, p_woT, bo, x, p_tmp, MTOK, DMODEL, DMODEL);

    // 4) LN1 -> y
    ln_kernel<<<MTOK, 256>>>(p_tmp, ln1_g, ln1_b, p_y);

    // 5) FFN1: relu(y*w1 + b1)
    mma_gemm<true, false><<<dim3(MTOK / 128, FF / 128), 256, GM_SMEM_BYTES>>>(
        p_y, p_w1T, b1, nullptr, p_ff, MTOK, FF, DMODEL);

    // 6) FFN2: ff*w2 + b2 + residual(y)
    mma_gemm<false, true><<<dim3(MTOK / 128, DMODEL / 128), 256, GM_SMEM_BYTES>>>(
        p_ff, p_w2T, b2, p_y, p_tmp, MTOK, DMODEL, FF);

    // 7) LN2 -> out
    ln_kernel<<<MTOK, 256>>>(p_tmp, ln2_g, ln2_b, out);
}

// round 8
// speedup vs baseline: 4.0703x; 2.4831x over previous
#include <cuda_runtime.h>
#include <math.h>
#include <stdint.h>

#define SEQ     2048
#define DMODEL  1024
#define NH      16
#define DHEAD   64
#define FF      4096
#define MTOK    8192   // B*S
#define NBATCH  4
#define QKVLD   3072   // q|k|v concatenated row stride

// ---------------- scratch (static device globals; no allocations) ----------------
__device__ float g_qkv [(size_t)MTOK * QKVLD];    // [B,S, q(1024)|k(1024)|v(1024)]
__device__ float g_attn[(size_t)MTOK * DMODEL];   // attention out (tf32-rounded)
__device__ float g_tmp [(size_t)MTOK * DMODEL];   // pre-LN sums
__device__ float g_y   [(size_t)MTOK * DMODEL];   // LN1 output (fp32, residual)
__device__ float g_ff  [(size_t)MTOK * FF];       // FFN hidden (tf32-rounded)
__device__ float g_wqkvT[(size_t)QKVLD * DMODEL]; // [3072,1024] tf32-rounded
__device__ float g_woT [(size_t)DMODEL * DMODEL];
__device__ float g_w1T [(size_t)FF * DMODEL];
__device__ float g_w2T [(size_t)DMODEL * FF];
__device__ float g_bqkv[QKVLD];

// ======================= helpers =======================
__device__ __forceinline__ uint32_t smem_u32(const void* p) {
    uint32_t a;
    asm("{ .reg .u64 t; cvta.to.shared.u64 t, %1; cvt.u32.u64 %0, t; }" : "=r"(a) : "l"(p));
    return a;
}
__device__ __forceinline__ void cp16(uint32_t dst, const void* src) {
    asm volatile("cp.async.cg.shared.global [%0], [%1], 16;" :: "r"(dst), "l"(src));
}
__device__ __forceinline__ uint32_t f2tf32(float f) {
    uint32_t r;
    asm("cvt.rna.tf32.f32 %0, %1;" : "=r"(r) : "f"(f));
    return r;
}
__device__ __forceinline__ void mma_tf32(float* d, const uint32_t* a, const uint32_t* b) {
    asm volatile("mma.sync.aligned.m16n8k8.row.col.f32.tf32.tf32.f32 "
                 "{%0,%1,%2,%3}, {%4,%5,%6,%7}, {%8,%9}, {%0,%1,%2,%3};"
                 : "+f"(d[0]), "+f"(d[1]), "+f"(d[2]), "+f"(d[3])
                 : "r"(a[0]), "r"(a[1]), "r"(a[2]), "r"(a[3]), "r"(b[0]), "r"(b[1]));
}

// =================================================================================
// TF32 mma.sync GEMM: C[M,N] = A[M,K] * Bt[N,K]^T + bias[N] (+resid) (relu) (round)
// CTA 128x128, BK=32, 128 threads (4 warps), warp tile 64x64.
// B (weights) are pre-rounded to tf32; A converted iff CVTA.
// =================================================================================
#define GM_LDK   36
#define GM_BUF   (128 * GM_LDK)
#define GM_SMEM_BYTES (4 * GM_BUF * 4)          // 73728

template<bool RELU, bool RESID, bool CVTA, bool ROUND>
__global__ void __launch_bounds__(128, 2) mma_gemm(
    const float* __restrict__ A, const float* __restrict__ Bt,
    const float* __restrict__ bias, const float* __restrict__ resid,
    float* __restrict__ C, int M, int N, int K)
{
    extern __shared__ __align__(16) float smf[];
    const uint32_t sb = smem_u32(smf);
    const int t    = threadIdx.x;
    const int lane = t & 31;
    const int w    = t >> 5;
    const int wm   = w & 1;          // 2 m-strips of 64
    const int wn   = w >> 1;         // 2 n-strips of 64
    const int qr   = lane >> 2;
    const int qc   = lane & 3;
    const int m0   = blockIdx.x * 128;
    const int n0   = blockIdx.y * 128;

    float acc[4][8][4];
#pragma unroll
    for (int mi = 0; mi < 4; mi++)
#pragma unroll
        for (int ni = 0; ni < 8; ni++)
#pragma unroll
            for (int k = 0; k < 4; k++) acc[mi][ni][k] = 0.f;

    const int NC = K >> 5;

    auto load_chunk = [&](int c, int s) {
        const int k0 = c << 5;
        const uint32_t aB = sb + (uint32_t)s * (GM_BUF * 4);
        const uint32_t bB = sb + (uint32_t)(2 * GM_BUF * 4) + (uint32_t)s * (GM_BUF * 4);
#pragma unroll
        for (int i = 0; i < 8; i++) {
            const int id = t + 128 * i;
            const int r = id >> 3, sg = id & 7;
            cp16(aB + (uint32_t)(r * (GM_LDK * 4) + sg * 16),
                 A + (size_t)(m0 + r) * K + k0 + sg * 4);
        }
#pragma unroll
        for (int i = 0; i < 8; i++) {
            const int id = t + 128 * i;
            const int r = id >> 3, sg = id & 7;
            cp16(bB + (uint32_t)(r * (GM_LDK * 4) + sg * 16),
                 Bt + (size_t)(n0 + r) * K + k0 + sg * 4);
        }
        asm volatile("cp.async.commit_group;" ::: "memory");
    };

    load_chunk(0, 0);

    for (int c = 0; c < NC; ++c) {
        if (c + 1 < NC) {
            load_chunk(c + 1, (c + 1) & 1);
            asm volatile("cp.async.wait_group 1;" ::: "memory");
        } else {
            asm volatile("cp.async.wait_group 0;" ::: "memory");
        }
        __syncthreads();

        const int buf = c & 1;
        const float*    Asf = smf + buf * GM_BUF;
        const uint32_t* Bsu = (const uint32_t*)(smf + 2 * GM_BUF + buf * GM_BUF);

#pragma unroll
        for (int kk = 0; kk < 4; kk++) {
            const int k0 = kk * 8;
            uint32_t af[4][4], bf[8][2];
#pragma unroll
            for (int mi = 0; mi < 4; mi++) {
                const float* p = Asf + (wm * 64 + mi * 16 + qr) * GM_LDK + k0 + qc;
                if (CVTA) {
                    af[mi][0] = f2tf32(p[0]);
                    af[mi][1] = f2tf32(p[8 * GM_LDK]);
                    af[mi][2] = f2tf32(p[4]);
                    af[mi][3] = f2tf32(p[8 * GM_LDK + 4]);
                } else {
                    af[mi][0] = __float_as_uint(p[0]);
                    af[mi][1] = __float_as_uint(p[8 * GM_LDK]);
                    af[mi][2] = __float_as_uint(p[4]);
                    af[mi][3] = __float_as_uint(p[8 * GM_LDK + 4]);
                }
            }
#pragma unroll
            for (int ni = 0; ni < 8; ni++) {
                const uint32_t* p = Bsu + (wn * 64 + ni * 8 + qr) * GM_LDK + k0 + qc;
                bf[ni][0] = p[0];
                bf[ni][1] = p[4];
            }
#pragma unroll
            for (int mi = 0; mi < 4; mi++)
#pragma unroll
                for (int ni = 0; ni < 8; ni++)
                    mma_tf32(acc[mi][ni], af[mi], bf[ni]);
        }
        __syncthreads();
    }

    // epilogue
#pragma unroll
    for (int mi = 0; mi < 4; mi++) {
        const int r0 = m0 + wm * 64 + mi * 16 + qr;
        const int r1 = r0 + 8;
#pragma unroll
        for (int ni = 0; ni < 8; ni++) {
            const int nb = n0 + wn * 64 + ni * 8 + qc * 2;
            const float b0 = bias[nb], b1 = bias[nb + 1];
            float2 v0, v1;
            v0.x = acc[mi][ni][0] + b0; v0.y = acc[mi][ni][1] + b1;
            v1.x = acc[mi][ni][2] + b0; v1.y = acc[mi][ni][3] + b1;
            if (RESID) {
                const float2 q0 = *(const float2*)(resid + (size_t)r0 * N + nb);
                const float2 q1 = *(const float2*)(resid + (size_t)r1 * N + nb);
                v0.x += q0.x; v0.y += q0.y; v1.x += q1.x; v1.y += q1.y;
            }
            if (RELU) {
                v0.x = fmaxf(v0.x, 0.f); v0.y = fmaxf(v0.y, 0.f);
                v1.x = fmaxf(v1.x, 0.f); v1.y = fmaxf(v1.y, 0.f);
            }
            if (ROUND) {
                v0.x = __uint_as_float(f2tf32(v0.x)); v0.y = __uint_as_float(f2tf32(v0.y));
                v1.x = __uint_as_float(f2tf32(v1.x)); v1.y = __uint_as_float(f2tf32(v1.y));
            }
            *(float2*)(C + (size_t)r0 * N + nb) = v0;
            *(float2*)(C + (size_t)r1 * N + nb) = v1;
        }
    }
}

// =================================================================================
// Transposes (tf32-round on output) + bias concat
// =================================================================================
__global__ void transpose_kernel(const float* __restrict__ in, float* __restrict__ out,
                                 int R, int C)
{
    __shared__ float tile[32][33];
    const int c0 = blockIdx.x * 32, r0 = blockIdx.y * 32;
#pragma unroll
    for (int i = 0; i < 4; i++)
        tile[threadIdx.y + 8 * i][threadIdx.x] =
            in[(size_t)(r0 + threadIdx.y + 8 * i) * C + c0 + threadIdx.x];
    __syncthreads();
#pragma unroll
    for (int i = 0; i < 4; i++)
        out[(size_t)(c0 + threadIdx.y + 8 * i) * R + r0 + threadIdx.x] =
            __uint_as_float(f2tf32(tile[threadIdx.x][threadIdx.y + 8 * i]));
}

__global__ void qkvw_transpose_kernel(const float* __restrict__ wq,
                                      const float* __restrict__ wk,
                                      const float* __restrict__ wv,
                                      float* __restrict__ out)
{
    __shared__ float tile[32][33];
    const int zh = blockIdx.z;
    const int z = zh >> 4, h = zh & 15;
    const float* src = (z == 0 ? wq : (z == 1 ? wk : wv)) + (size_t)h * DMODEL * DHEAD;
    float* dst = out + ((size_t)(z * 16 + h)) * DHEAD * DMODEL;
    const int c0 = blockIdx.x * 32, r0 = blockIdx.y * 32;
#pragma unroll
    for (int i = 0; i < 4; i++)
        tile[threadIdx.y + 8 * i][threadIdx.x] =
            src[(size_t)(r0 + threadIdx.y + 8 * i) * DHEAD + c0 + threadIdx.x];
    __syncthreads();
#pragma unroll
    for (int i = 0; i < 4; i++)
        dst[(size_t)(c0 + threadIdx.y + 8 * i) * DMODEL + r0 + threadIdx.x] =
            __uint_as_float(f2tf32(tile[threadIdx.x][threadIdx.y + 8 * i]));
}

__global__ void biascat_kernel(const float* __restrict__ bq, const float* __restrict__ bk,
                               const float* __restrict__ bv, float* __restrict__ out)
{
    const int i = blockIdx.x * 256 + threadIdx.x;
    out[i] = (i < 1024) ? bq[i] : ((i < 2048) ? bk[i - 1024] : bv[i - 2048]);
}

// =================================================================================
// Fused flash attention on tf32 mma.sync.
// CTA: 128 q-rows of one (b,head); 128 threads = 4 warps, warp = 32 q-rows.
// Per 64-key tile: S=QK^T (mma), online softmax (exp2), P->smem (tf32), O+=PV (mma).
// =================================================================================
#define AQ_LD 68
#define AV_LD 72
#define AT_QOFF 0
#define AT_KOFF (128 * AQ_LD)             // 8704
#define AT_VOFF (AT_KOFF + 64 * AQ_LD)    // 13056
#define AT_POFF (AT_VOFF + 64 * AV_LD)    // 17664
#define AT_WORDS (AT_POFF + 128 * AQ_LD)  // 26368
#define ATT_SMEM_BYTES (AT_WORDS * 4)     // 105472

__global__ void __launch_bounds__(128) attn_mma_kernel(
    const float* __restrict__ qkv, float* __restrict__ obuf)
{
    extern __shared__ __align__(16) uint32_t smu[];
    float* smf = (float*)smu;
    const uint32_t sb = smem_u32(smu);
    const int t = threadIdx.x, lane = t & 31, w = t >> 5;
    const int qr = lane >> 2, qc = lane & 3;
    const int mw = w * 32;
    const int bh = blockIdx.y;
    const int b = bh >> 4, hd = bh & 15;
    const int q0 = blockIdx.x * 128;

    // Q -> Qs, scaled by 1/sqrt(64) * log2(e), tf32 bits
    {
        const float sc = 0.125f * 1.4426950408889634f;
        const float* Q = qkv + ((size_t)(b * SEQ + q0 + t)) * QKVLD + hd * 64;
#pragma unroll
        for (int c = 0; c < 64; c += 4) {
            const float4 v = *(const float4*)(Q + c);
            smu[AT_QOFF + t * AQ_LD + c + 0] = f2tf32(v.x * sc);
            smu[AT_QOFF + t * AQ_LD + c + 1] = f2tf32(v.y * sc);
            smu[AT_QOFF + t * AQ_LD + c + 2] = f2tf32(v.z * sc);
            smu[AT_QOFF + t * AQ_LD + c + 3] = f2tf32(v.w * sc);
        }
    }

    float o[2][8][4];
    float mrow[2][2], lrow[2][2];
#pragma unroll
    for (int mi = 0; mi < 2; mi++) {
        mrow[mi][0] = -INFINITY; mrow[mi][1] = -INFINITY;
        lrow[mi][0] = 0.f;       lrow[mi][1] = 0.f;
#pragma unroll
        for (int ni = 0; ni < 8; ni++)
#pragma unroll
            for (int k = 0; k < 4; k++) o[mi][ni][k] = 0.f;
    }

    const float* Kp = qkv + (size_t)b * SEQ * QKVLD + 1024 + hd * 64;
    const float* Vp = qkv + (size_t)b * SEQ * QKVLD + 2048 + hd * 64;

    for (int kt = 0; kt < SEQ / 64; kt++) {
        // K/V tile loads: 64 rows x 64 cols = 64 rows x 16 float4-segments
#pragma unroll
        for (int i = 0; i < 8; i++) {
            const int id = t + 128 * i;
            const int r = id >> 4, sg = id & 15;
            cp16(sb + 4u * (AT_KOFF + r * AQ_LD + sg * 4),
                 Kp + (size_t)(kt * 64 + r) * QKVLD + sg * 4);
        }
#pragma unroll
        for (int i = 0; i < 8; i++) {
            const int id = t + 128 * i;
            const int r = id >> 4, sg = id & 15;
            cp16(sb + 4u * (AT_VOFF + r * AV_LD + sg * 4),
                 Vp + (size_t)(kt * 64 + r) * QKVLD + sg * 4);
        }
        asm volatile("cp.async.commit_group;\n\tcp.async.wait_group 0;" ::: "memory");
        __syncthreads();

        // S = Q K^T
        float s[2][8][4];
#pragma unroll
        for (int mi = 0; mi < 2; mi++)
#pragma unroll
            for (int ni = 0; ni < 8; ni++)
#pragma unroll
                for (int k = 0; k < 4; k++) s[mi][ni][k] = 0.f;

#pragma unroll
        for (int kk = 0; kk < 8; kk++) {
            uint32_t a[2][4], bb[2];
#pragma unroll
            for (int mi = 0; mi < 2; mi++) {
                const uint32_t* p = smu + AT_QOFF + (mw + mi * 16 + qr) * AQ_LD + kk * 8 + qc;
                a[mi][0] = p[0]; a[mi][1] = p[8 * AQ_LD];
                a[mi][2] = p[4]; a[mi][3] = p[8 * AQ_LD + 4];
            }
#pragma unroll
            for (int ni = 0; ni < 8; ni++) {
                const float* p = smf + AT_KOFF + (ni * 8 + qr) * AQ_LD + kk * 8 + qc;
                bb[0] = f2tf32(p[0]); bb[1] = f2tf32(p[4]);
                mma_tf32(s[0][ni], a[0], bb);
                mma_tf32(s[1][ni], a[1], bb);
            }
        }

        // online softmax (base-2 domain)
#pragma unroll
        for (int mi = 0; mi < 2; mi++)
#pragma unroll
        for (int h2 = 0; h2 < 2; h2++) {
            float vm = -INFINITY;
#pragma unroll
            for (int ni = 0; ni < 8; ni++)
                vm = fmaxf(vm, fmaxf(s[mi][ni][2 * h2], s[mi][ni][2 * h2 + 1]));
            vm = fmaxf(vm, __shfl_xor_sync(0xffffffffu, vm, 1));
            vm = fmaxf(vm, __shfl_xor_sync(0xffffffffu, vm, 2));
            const float mn = fmaxf(mrow[mi][h2], vm);
            const float alpha = exp2f(mrow[mi][h2] - mn);
            mrow[mi][h2] = mn;
            float rs = 0.f;
#pragma unroll
            for (int ni = 0; ni < 8; ni++) {
                const float p0 = exp2f(s[mi][ni][2 * h2] - mn);
                const float p1 = exp2f(s[mi][ni][2 * h2 + 1] - mn);
                s[mi][ni][2 * h2] = p0; s[mi][ni][2 * h2 + 1] = p1;
                rs += p0 + p1;
            }
            rs += __shfl_xor_sync(0xffffffffu, rs, 1);
            rs += __shfl_xor_sync(0xffffffffu, rs, 2);
            lrow[mi][h2] = lrow[mi][h2] * alpha + rs;
#pragma unroll
            for (int ni = 0; ni < 8; ni++) {
                o[mi][ni][2 * h2]     *= alpha;
                o[mi][ni][2 * h2 + 1] *= alpha;
            }
        }

        // P -> smem (tf32 bits); warp-private rows
#pragma unroll
        for (int mi = 0; mi < 2; mi++)
#pragma unroll
        for (int ni = 0; ni < 8; ni++) {
            uint32_t* p = smu + AT_POFF + (mw + mi * 16 + qr) * AQ_LD + ni * 8 + qc * 2;
            p[0] = f2tf32(s[mi][ni][0]);
            p[1] = f2tf32(s[mi][ni][1]);
            p[8 * AQ_LD]     = f2tf32(s[mi][ni][2]);
            p[8 * AQ_LD + 1] = f2tf32(s[mi][ni][3]);
        }
        __syncwarp();

        // O += P V
#pragma unroll
        for (int kk = 0; kk < 8; kk++) {
            uint32_t a[2][4], bb[2];
#pragma unroll
            for (int mi = 0; mi < 2; mi++) {
                const uint32_t* p = smu + AT_POFF + (mw + mi * 16 + qr) * AQ_LD + kk * 8 + qc;
                a[mi][0] = p[0]; a[mi][1] = p[8 * AQ_LD];
                a[mi][2] = p[4]; a[mi][3] = p[8 * AQ_LD + 4];
            }
#pragma unroll
            for (int ni = 0; ni < 8; ni++) {
                const float* pv = smf + AT_VOFF + (kk * 8 + qc) * AV_LD + ni * 8 + qr;
                bb[0] = f2tf32(pv[0]);
                bb[1] = f2tf32(pv[4 * AV_LD]);
                mma_tf32(o[0][ni], a[0], bb);
                mma_tf32(o[1][ni], a[1], bb);
            }
        }
        __syncthreads();
    }

    // epilogue: O / l, tf32-round (feeds O-proj), write [B,S,H*DH]
#pragma unroll
    for (int mi = 0; mi < 2; mi++) {
        const float inv0 = 1.f / lrow[mi][0];
        const float inv1 = 1.f / lrow[mi][1];
        const int r0 = q0 + mw + mi * 16 + qr;
        const int r1 = r0 + 8;
        float* d0 = obuf + (size_t)(b * SEQ + r0) * DMODEL + hd * 64;
        float* d1 = obuf + (size_t)(b * SEQ + r1) * DMODEL + hd * 64;
#pragma unroll
        for (int ni = 0; ni < 8; ni++) {
            const int nb = ni * 8 + qc * 2;
            float2 v0, v1;
            v0.x = __uint_as_float(f2tf32(o[mi][ni][0] * inv0));
            v0.y = __uint_as_float(f2tf32(o[mi][ni][1] * inv0));
            v1.x = __uint_as_float(f2tf32(o[mi][ni][2] * inv1));
            v1.y = __uint_as_float(f2tf32(o[mi][ni][3] * inv1));
            *(float2*)(d0 + nb) = v0;
            *(float2*)(d1 + nb) = v1;
        }
    }
}

// =================================================================================
// LayerNorm over D=1024
// =================================================================================
__global__ void __launch_bounds__(256) ln_kernel(
    const float* __restrict__ in, const float* __restrict__ g,
    const float* __restrict__ b, float* __restrict__ out)
{
    const int row = blockIdx.x;
    const int tid = threadIdx.x;
    const float4 v = ((const float4*)(in + (size_t)row * DMODEL))[tid];

    float s  = v.x + v.y + v.z + v.w;
    float sq = v.x * v.x + v.y * v.y + v.z * v.z + v.w * v.w;
#pragma unroll
    for (int off = 16; off > 0; off >>= 1) {
        s  += __shfl_xor_sync(0xffffffffu, s,  off);
        sq += __shfl_xor_sync(0xffffffffu, sq, off);
    }
    __shared__ float ss[8], ssq[8];
    if ((tid & 31) == 0) { ss[tid >> 5] = s; ssq[tid >> 5] = sq; }
    __syncthreads();
    s = 0.f; sq = 0.f;
#pragma unroll
    for (int i = 0; i < 8; i++) { s += ss[i]; sq += ssq[i]; }

    const float mu   = s * (1.f / DMODEL);
    const float var  = sq * (1.f / DMODEL) - mu * mu;
    const float rstd = rsqrtf(var + 1e-5f);

    const float4 gg = ((const float4*)g)[tid];
    const float4 bb = ((const float4*)b)[tid];
    float4 r;
    r.x = (v.x - mu) * rstd * gg.x + bb.x;
    r.y = (v.y - mu) * rstd * gg.y + bb.y;
    r.z = (v.z - mu) * rstd * gg.z + bb.z;
    r.w = (v.w - mu) * rstd * gg.w + bb.w;
    ((float4*)(out + (size_t)row * DMODEL))[tid] = r;
}

// =================================================================================
// Host launcher
// =================================================================================
extern "C" void kernel_launch(void* const* d_in, const int* in_sizes, int n_in,
                              void* d_out, int out_size)
{
    (void)in_sizes; (void)n_in; (void)out_size;
    const float* x     = (const float*)d_in[0];
    const float* wq    = (const float*)d_in[1];
    const float* bq    = (const float*)d_in[2];
    const float* wk    = (const float*)d_in[3];
    const float* bk    = (const float*)d_in[4];
    const float* wv    = (const float*)d_in[5];
    const float* bv    = (const float*)d_in[6];
    const float* wo    = (const float*)d_in[7];
    const float* bo    = (const float*)d_in[8];
    const float* ln1_g = (const float*)d_in[9];
    const float* ln1_b = (const float*)d_in[10];
    const float* w1    = (const float*)d_in[11];
    const float* b1    = (const float*)d_in[12];
    const float* w2    = (const float*)d_in[13];
    const float* b2    = (const float*)d_in[14];
    const float* ln2_g = (const float*)d_in[15];
    const float* ln2_b = (const float*)d_in[16];
    float* out = (float*)d_out;

    static float *p_qkv = nullptr, *p_attn = nullptr, *p_tmp = nullptr, *p_y = nullptr,
                 *p_ff = nullptr, *p_wqkvT = nullptr, *p_woT = nullptr, *p_w1T = nullptr,
                 *p_w2T = nullptr, *p_bqkv = nullptr;
    if (!p_qkv) {
        cudaGetSymbolAddress((void**)&p_qkv,   g_qkv);
        cudaGetSymbolAddress((void**)&p_attn,  g_attn);
        cudaGetSymbolAddress((void**)&p_tmp,   g_tmp);
        cudaGetSymbolAddress((void**)&p_y,     g_y);
        cudaGetSymbolAddress((void**)&p_ff,    g_ff);
        cudaGetSymbolAddress((void**)&p_wqkvT, g_wqkvT);
        cudaGetSymbolAddress((void**)&p_woT,   g_woT);
        cudaGetSymbolAddress((void**)&p_w1T,   g_w1T);
        cudaGetSymbolAddress((void**)&p_w2T,   g_w2T);
        cudaGetSymbolAddress((void**)&p_bqkv,  g_bqkv);
        cudaFuncSetAttribute(attn_mma_kernel,
                             cudaFuncAttributeMaxDynamicSharedMemorySize, ATT_SMEM_BYTES);
        cudaFuncSetAttribute(mma_gemm<false, false, true, false>,
                             cudaFuncAttributeMaxDynamicSharedMemorySize, GM_SMEM_BYTES);
        cudaFuncSetAttribute(mma_gemm<false, true, false, false>,
                             cudaFuncAttributeMaxDynamicSharedMemorySize, GM_SMEM_BYTES);
        cudaFuncSetAttribute(mma_gemm<true, false, true, true>,
                             cudaFuncAttributeMaxDynamicSharedMemorySize, GM_SMEM_BYTES);
        cudaFuncSetAttribute(mma_gemm<false, true, false, true>,
                             cudaFuncAttributeMaxDynamicSharedMemorySize, GM_SMEM_BYTES);
    }

    // 0) weight transposes (tf32 pre-round) + bias concat
    qkvw_transpose_kernel<<<dim3(2, 32, 48), dim3(32, 8)>>>(wq, wk, wv, p_wqkvT);
    transpose_kernel<<<dim3(32, 32),  dim3(32, 8)>>>(wo, p_woT, DMODEL, DMODEL);
    transpose_kernel<<<dim3(128, 32), dim3(32, 8)>>>(w1, p_w1T, DMODEL, FF);
    transpose_kernel<<<dim3(32, 128), dim3(32, 8)>>>(w2, p_w2T, FF, DMODEL);
    biascat_kernel<<<12, 256>>>(bq, bk, bv, p_bqkv);

    // 1) fused QKV projection (A = x, cvt in-kernel)
    mma_gemm<false, false, true, false><<<dim3(MTOK / 128, QKVLD / 128), 128, GM_SMEM_BYTES>>>(
        x, p_wqkvT, p_bqkv, nullptr, p_qkv, MTOK, QKVLD, DMODEL);

    // 2) fused attention (tf32 mma), output tf32-rounded
    attn_mma_kernel<<<dim3(SEQ / 128, NBATCH * NH), 128, ATT_SMEM_BYTES>>>(p_qkv, p_attn);

    // 3) output projection + bias + residual(x)  (A pre-rounded)
    mma_gemm<false, true, false, false><<<dim3(MTOK / 128, DMODEL / 128), 128, GM_SMEM_BYTES>>>(
        p_attn, p_woT, bo, x, p_tmp, MTOK, DMODEL, DMODEL);

    // 4) LN1 -> y (fp32, residual stream)
    ln_kernel<<<MTOK, 256>>>(p_tmp, ln1_g, ln1_b, p_y);

    // 5) FFN1: relu(y*w1 + b1), output tf32-rounded (A = y, cvt in-kernel)
    mma_gemm<true, false, true, true><<<dim3(MTOK / 128, FF / 128), 128, GM_SMEM_BYTES>>>(
        p_y, p_w1T, b1, nullptr, p_ff, MTOK, FF, DMODEL);

    // 6) FFN2: ff*w2 + b2 + residual(y)  (A pre-rounded)
    mma_gemm<false, true, false, true><<<dim3(MTOK / 128, DMODEL / 128), 128, GM_SMEM_BYTES>>>(
        p_ff, p_w2T, b2, p_y, p_tmp, MTOK, DMODEL, FF);

    // 7) LN2 -> out
    ln_kernel<<<MTOK, 256>>>(p_tmp, ln2_g, ln2_b, out);
}

// round 9
// speedup vs baseline: 6.4521x; 1.5852x over previous
#include <cuda_runtime.h>
#include <cuda_fp16.h>
#include <math.h>
#include <stdint.h>

#define SEQ     2048
#define DMODEL  1024
#define NH      16
#define DHEAD   64
#define FF      4096
#define MTOK    8192   // B*S
#define NBATCH  4
#define QKVLD   3072   // q|k|v concatenated row stride (halfs)

// ---------------- scratch (static device globals; no allocations) ----------------
__device__ __half g_qkv [(size_t)MTOK * QKVLD];   // fp16 q|k|v
__device__ __half g_attn[(size_t)MTOK * DMODEL];  // attention out fp16
__device__ float  g_tmp [(size_t)MTOK * DMODEL];  // pre-LN sums fp32
__device__ float  g_y   [(size_t)MTOK * DMODEL];  // LN1 out fp32 (residual)
__device__ __half g_yh  [(size_t)MTOK * DMODEL];  // LN1 out fp16 (FFN1 A)
__device__ __half g_ff  [(size_t)MTOK * FF];      // FFN hidden fp16
__device__ __half g_xh  [(size_t)MTOK * DMODEL];  // x fp16 (QKV A)
__device__ __half g_wqkvT[(size_t)QKVLD * DMODEL];
__device__ __half g_woT [(size_t)DMODEL * DMODEL];
__device__ __half g_w1T [(size_t)FF * DMODEL];
__device__ __half g_w2T [(size_t)DMODEL * FF];
__device__ float  g_bqkv[QKVLD];

// ======================= helpers =======================
__device__ __forceinline__ uint32_t smem_u32(const void* p) {
    uint32_t a;
    asm("{ .reg .u64 t; cvta.to.shared.u64 t, %1; cvt.u32.u64 %0, t; }" : "=r"(a) : "l"(p));
    return a;
}
__device__ __forceinline__ void cp16(uint32_t dst, const void* src) {
    asm volatile("cp.async.cg.shared.global [%0], [%1], 16;" :: "r"(dst), "l"(src));
}
__device__ __forceinline__ void mma_f16(float* d, const uint32_t* a, const uint32_t* b) {
    asm volatile("mma.sync.aligned.m16n8k16.row.col.f32.f16.f16.f32 "
                 "{%0,%1,%2,%3}, {%4,%5,%6,%7}, {%8,%9}, {%0,%1,%2,%3};"
                 : "+f"(d[0]), "+f"(d[1]), "+f"(d[2]), "+f"(d[3])
                 : "r"(a[0]), "r"(a[1]), "r"(a[2]), "r"(a[3]), "r"(b[0]), "r"(b[1]));
}

// =================================================================================
// FP16 mma.sync GEMM: C[M,N] = A[M,K]*Bt[N,K]^T + bias (+resid fp32) (relu)
// CTA 128x128, BK=32, 128 threads, warp tile 64x64, 3-stage cp.async.
// Output: fp32 (Cf) or fp16 (Ch) per OUTH.
// =================================================================================
#define GH_LDH 40                  // halfs per smem row
#define GH_LDW 20                  // 32-bit words per smem row
#define GH_STAGE_W (128 * GH_LDW)  // 2560 words per tile-stage
#define GH_STAGES 3
#define GM_SMEM_BYTES (2 * GH_STAGES * GH_STAGE_W * 4)  // 61440

template<bool RELU, bool RESID, bool OUTH>
__global__ void __launch_bounds__(128, 2) mma_gemm(
    const __half* __restrict__ A, const __half* __restrict__ Bt,
    const float* __restrict__ bias, const float* __restrict__ resid,
    float* __restrict__ Cf, __half* __restrict__ Ch, int M, int N, int K)
{
    extern __shared__ __align__(16) uint32_t smw[];
    const uint32_t sb = smem_u32(smw);
    const int t    = threadIdx.x;
    const int lane = t & 31;
    const int w    = t >> 5;
    const int wm   = w & 1;
    const int wn   = w >> 1;
    const int qr   = lane >> 2;
    const int qc   = lane & 3;
    const int m0   = blockIdx.x * 128;
    const int n0   = blockIdx.y * 128;

    float acc[4][8][4];
#pragma unroll
    for (int mi = 0; mi < 4; mi++)
#pragma unroll
        for (int ni = 0; ni < 8; ni++)
#pragma unroll
            for (int k = 0; k < 4; k++) acc[mi][ni][k] = 0.f;

    const int NC = K >> 5;

    auto load_chunk = [&](int c, int s) {
        const int k0 = c << 5;
#pragma unroll
        for (int i = 0; i < 4; i++) {
            const int id = t + 128 * i;
            const int r = id >> 2, sg = id & 3;
            cp16(sb + 4u * (s * GH_STAGE_W + r * GH_LDW + sg * 4),
                 A + (size_t)(m0 + r) * K + k0 + sg * 8);
        }
#pragma unroll
        for (int i = 0; i < 4; i++) {
            const int id = t + 128 * i;
            const int r = id >> 2, sg = id & 3;
            cp16(sb + 4u * (GH_STAGES * GH_STAGE_W + s * GH_STAGE_W + r * GH_LDW + sg * 4),
                 Bt + (size_t)(n0 + r) * K + k0 + sg * 8);
        }
        asm volatile("cp.async.commit_group;" ::: "memory");
    };

    load_chunk(0, 0);
    load_chunk(1, 1);

    int scur = 0;
    for (int c = 0; c < NC; ++c) {
        if (c + 2 < NC) {
            int s2 = scur + 2; if (s2 >= GH_STAGES) s2 -= GH_STAGES;
            load_chunk(c + 2, s2);
            asm volatile("cp.async.wait_group 2;" ::: "memory");
        } else if (c + 1 < NC) {
            asm volatile("cp.async.wait_group 1;" ::: "memory");
        } else {
            asm volatile("cp.async.wait_group 0;" ::: "memory");
        }
        __syncthreads();

        const uint32_t* Aw = smw + scur * GH_STAGE_W;
        const uint32_t* Bw = smw + GH_STAGES * GH_STAGE_W + scur * GH_STAGE_W;

#pragma unroll
        for (int kk = 0; kk < 2; kk++) {
            uint32_t af[4][4], bf[8][2];
#pragma unroll
            for (int mi = 0; mi < 4; mi++) {
                const int base = (wm * 64 + mi * 16 + qr) * GH_LDW + kk * 8 + qc;
                af[mi][0] = Aw[base];
                af[mi][1] = Aw[base + 8 * GH_LDW];
                af[mi][2] = Aw[base + 4];
                af[mi][3] = Aw[base + 8 * GH_LDW + 4];
            }
#pragma unroll
            for (int ni = 0; ni < 8; ni++) {
                const int bbx = (wn * 64 + ni * 8 + qr) * GH_LDW + kk * 8 + qc;
                bf[ni][0] = Bw[bbx];
                bf[ni][1] = Bw[bbx + 4];
            }
#pragma unroll
            for (int mi = 0; mi < 4; mi++)
#pragma unroll
                for (int ni = 0; ni < 8; ni++)
                    mma_f16(acc[mi][ni], af[mi], bf[ni]);
        }
        __syncthreads();
        if (++scur == GH_STAGES) scur = 0;
    }

    // epilogue
#pragma unroll
    for (int mi = 0; mi < 4; mi++) {
        const int r0 = m0 + wm * 64 + mi * 16 + qr;
        const int r1 = r0 + 8;
#pragma unroll
        for (int ni = 0; ni < 8; ni++) {
            const int nb = n0 + wn * 64 + ni * 8 + qc * 2;
            const float b0 = bias[nb], b1 = bias[nb + 1];
            float2 v0, v1;
            v0.x = acc[mi][ni][0] + b0; v0.y = acc[mi][ni][1] + b1;
            v1.x = acc[mi][ni][2] + b0; v1.y = acc[mi][ni][3] + b1;
            if (RESID) {
                const float2 q0 = *(const float2*)(resid + (size_t)r0 * N + nb);
                const float2 q1 = *(const float2*)(resid + (size_t)r1 * N + nb);
                v0.x += q0.x; v0.y += q0.y; v1.x += q1.x; v1.y += q1.y;
            }
            if (RELU) {
                v0.x = fmaxf(v0.x, 0.f); v0.y = fmaxf(v0.y, 0.f);
                v1.x = fmaxf(v1.x, 0.f); v1.y = fmaxf(v1.y, 0.f);
            }
            if (OUTH) {
                *(__half2*)(Ch + (size_t)r0 * N + nb) = __floats2half2_rn(v0.x, v0.y);
                *(__half2*)(Ch + (size_t)r1 * N + nb) = __floats2half2_rn(v1.x, v1.y);
            } else {
                *(float2*)(Cf + (size_t)r0 * N + nb) = v0;
                *(float2*)(Cf + (size_t)r1 * N + nb) = v1;
            }
        }
    }
}

// =================================================================================
// Producers: fp32->fp16 convert, transposes (fp16 out), bias concat
// =================================================================================
__global__ void f2h_kernel(const float* __restrict__ in, __half* __restrict__ out)
{
    const int i = (blockIdx.x * 256 + threadIdx.x) * 4;
    const float4 v = *(const float4*)(in + i);
    *(__half2*)(out + i)     = __floats2half2_rn(v.x, v.y);
    *(__half2*)(out + i + 2) = __floats2half2_rn(v.z, v.w);
}

__global__ void transpose_kernel(const float* __restrict__ in, __half* __restrict__ out,
                                 int R, int C)
{
    __shared__ float tile[32][33];
    const int c0 = blockIdx.x * 32, r0 = blockIdx.y * 32;
#pragma unroll
    for (int i = 0; i < 4; i++)
        tile[threadIdx.y + 8 * i][threadIdx.x] =
            in[(size_t)(r0 + threadIdx.y + 8 * i) * C + c0 + threadIdx.x];
    __syncthreads();
#pragma unroll
    for (int i = 0; i < 4; i++)
        out[(size_t)(c0 + threadIdx.y + 8 * i) * R + r0 + threadIdx.x] =
            __float2half_rn(tile[threadIdx.x][threadIdx.y + 8 * i]);
}

__global__ void qkvw_transpose_kernel(const float* __restrict__ wq,
                                      const float* __restrict__ wk,
                                      const float* __restrict__ wv,
                                      __half* __restrict__ out)
{
    __shared__ float tile[32][33];
    const int zh = blockIdx.z;
    const int z = zh >> 4, h = zh & 15;
    const float* src = (z == 0 ? wq : (z == 1 ? wk : wv)) + (size_t)h * DMODEL * DHEAD;
    __half* dst = out + ((size_t)(z * 16 + h)) * DHEAD * DMODEL;
    const int c0 = blockIdx.x * 32, r0 = blockIdx.y * 32;
#pragma unroll
    for (int i = 0; i < 4; i++)
        tile[threadIdx.y + 8 * i][threadIdx.x] =
            src[(size_t)(r0 + threadIdx.y + 8 * i) * DHEAD + c0 + threadIdx.x];
    __syncthreads();
#pragma unroll
    for (int i = 0; i < 4; i++)
        dst[(size_t)(c0 + threadIdx.y + 8 * i) * DMODEL + r0 + threadIdx.x] =
            __float2half_rn(tile[threadIdx.x][threadIdx.y + 8 * i]);
}

__global__ void biascat_kernel(const float* __restrict__ bq, const float* __restrict__ bk,
                               const float* __restrict__ bv, float* __restrict__ out)
{
    const int i = blockIdx.x * 256 + threadIdx.x;
    out[i] = (i < 1024) ? bq[i] : ((i < 2048) ? bk[i - 1024] : bv[i - 2048]);
}

// =================================================================================
// Fused flash attention, fp16 m16n8k16 mma.
// CTA: 128 q-rows of one (b,head); 256 threads = 8 warps, warp = 16 q-rows.
// K double-buffered via cp.async; V register-staged + smem-transposed; Q frags in regs.
// =================================================================================
#define AH_LD  72    // halfs per smem row
#define AH_LDW 36    // words per smem row
#define AHT_QOFF 0                       // 128*36 = 4608 words
#define AHT_KOFF 4608                    // 2 bufs x 64*36 = 4608 words
#define AHT_VOFF (4608 + 4608)           // Vt: 64*36 = 2304 words
#define AHT_POFF (AHT_VOFF + 2304)       // P: 128*36 = 4608 words
#define AHT_WORDS (AHT_POFF + 4608)      // 16128 words
#define ATT_SMEM_BYTES (AHT_WORDS * 4)   // 64512

__global__ void __launch_bounds__(256, 2) attn_mma_kernel(
    const __half* __restrict__ qkv, __half* __restrict__ obuf)
{
    extern __shared__ __align__(16) uint32_t smu[];
    __half* smh = (__half*)smu;
    const uint32_t sb = smem_u32(smu);
    const int t = threadIdx.x, lane = t & 31, w = t >> 5;
    const int qr = lane >> 2, qc = lane & 3;
    const int mw = w * 16;
    const int bh = blockIdx.y;
    const int b = bh >> 4, hd = bh & 15;
    const int q0 = blockIdx.x * 128;

    // ---- stage Q (scaled by 1/sqrt(64)*log2e) as fp16 ----
    {
        const float sc = 0.125f * 1.4426950408889634f;
        const int row = t >> 1, hoff = (t & 1) * 32;
        const __half* Q = qkv + (size_t)(b * SEQ + q0 + row) * QKVLD + hd * 64 + hoff;
        __half* dst = smh + (size_t)row * AH_LD + hoff;   // AHT_QOFF = 0
#pragma unroll
        for (int c = 0; c < 32; c += 2) {
            const float2 f = __half22float2(*(const __half2*)(Q + c));
            *(__half2*)(dst + c) = __floats2half2_rn(f.x * sc, f.y * sc);
        }
    }

    const __half* Kp = qkv + (size_t)b * SEQ * QKVLD + 1024 + hd * 64;
    const __half* Vp = qkv + (size_t)b * SEQ * QKVLD + 2048 + hd * 64;

    auto load_k = [&](int kt, int s) {
#pragma unroll
        for (int i = 0; i < 2; i++) {
            const int id = t + 256 * i;
            const int r = id >> 3, sg = id & 7;
            cp16(sb + 4u * (AHT_KOFF + s * 2304 + r * AH_LDW) + sg * 16,
                 Kp + (size_t)(kt * 64 + r) * QKVLD + sg * 8);
        }
        asm volatile("cp.async.commit_group;" ::: "memory");
    };

    // V register staging: thread owns (kv = t>>2, 16 cols at (t&3)*16)
    const int vkv = t >> 2, vseg = (t & 3) * 16;
    float4 vr0, vr1;
    auto ldg_v = [&](int kt) {
        const float4* p = (const float4*)(Vp + (size_t)(kt * 64 + vkv) * QKVLD + vseg);
        vr0 = p[0]; vr1 = p[1];
    };

    load_k(0, 0);
    ldg_v(0);
    __syncthreads();   // Q visible

    // Q fragments -> registers (fixed for whole kernel)
    uint32_t qa[4][4];
    {
        const uint32_t* Qw = smu;  // AHT_QOFF = 0
#pragma unroll
        for (int kk = 0; kk < 4; kk++) {
            const int base = (mw + qr) * AH_LDW + kk * 8 + qc;
            qa[kk][0] = Qw[base];
            qa[kk][1] = Qw[base + 8 * AH_LDW];
            qa[kk][2] = Qw[base + 4];
            qa[kk][3] = Qw[base + 8 * AH_LDW + 4];
        }
    }

    float o[8][4];
    float mrow[2] = { -INFINITY, -INFINITY };
    float lrow[2] = { 0.f, 0.f };
#pragma unroll
    for (int ni = 0; ni < 8; ni++)
#pragma unroll
        for (int k = 0; k < 4; k++) o[ni][k] = 0.f;

    for (int kt = 0; kt < SEQ / 64; kt++) {
        const int buf = kt & 1;

        // store V regs transposed -> Vt[e][kv]
        {
            __half* vt = smh + 2 * AHT_VOFF;
            const __half* h0 = (const __half*)&vr0;
            const __half* h1 = (const __half*)&vr1;
#pragma unroll
            for (int j = 0; j < 8; j++) vt[(vseg + j) * AH_LD + vkv] = h0[j];
#pragma unroll
            for (int j = 0; j < 8; j++) vt[(vseg + 8 + j) * AH_LD + vkv] = h1[j];
        }
        if (kt + 1 < SEQ / 64) load_k(kt + 1, 1 - buf);
        ldg_v(kt + 1 < SEQ / 64 ? kt + 1 : SEQ / 64 - 1);   // prefetch next V
        if (kt + 1 < SEQ / 64)
            asm volatile("cp.async.wait_group 1;" ::: "memory");
        else
            asm volatile("cp.async.wait_group 0;" ::: "memory");
        __syncthreads();

        const uint32_t* Kw = smu + AHT_KOFF + buf * 2304;

        // S = Q K^T
        float s[8][4];
#pragma unroll
        for (int ni = 0; ni < 8; ni++)
#pragma unroll
            for (int k = 0; k < 4; k++) s[ni][k] = 0.f;
#pragma unroll
        for (int kk = 0; kk < 4; kk++) {
#pragma unroll
            for (int ni = 0; ni < 8; ni++) {
                const int bbx = (ni * 8 + qr) * AH_LDW + kk * 8 + qc;
                uint32_t bfr[2] = { Kw[bbx], Kw[bbx + 4] };
                mma_f16(s[ni], qa[kk], bfr);
            }
        }

        // online softmax (base-2)
#pragma unroll
        for (int h2 = 0; h2 < 2; h2++) {
            float vm = -INFINITY;
#pragma unroll
            for (int ni = 0; ni < 8; ni++)
                vm = fmaxf(vm, fmaxf(s[ni][2 * h2], s[ni][2 * h2 + 1]));
            vm = fmaxf(vm, __shfl_xor_sync(0xffffffffu, vm, 1));
            vm = fmaxf(vm, __shfl_xor_sync(0xffffffffu, vm, 2));
            const float mn = fmaxf(mrow[h2], vm);
            const float alpha = exp2f(mrow[h2] - mn);
            mrow[h2] = mn;
            float rs = 0.f;
#pragma unroll
            for (int ni = 0; ni < 8; ni++) {
                const float p0 = exp2f(s[ni][2 * h2] - mn);
                const float p1 = exp2f(s[ni][2 * h2 + 1] - mn);
                s[ni][2 * h2] = p0; s[ni][2 * h2 + 1] = p1;
                rs += p0 + p1;
            }
            rs += __shfl_xor_sync(0xffffffffu, rs, 1);
            rs += __shfl_xor_sync(0xffffffffu, rs, 2);
            lrow[h2] = lrow[h2] * alpha + rs;
#pragma unroll
            for (int ni = 0; ni < 8; ni++) {
                o[ni][2 * h2]     *= alpha;
                o[ni][2 * h2 + 1] *= alpha;
            }
        }

        // P -> smem fp16 (warp-private rows)
        {
            __half* Ph = smh + 2 * AHT_POFF;
#pragma unroll
            for (int ni = 0; ni < 8; ni++) {
                *(__half2*)(Ph + (mw + qr) * AH_LD + ni * 8 + qc * 2) =
                    __floats2half2_rn(s[ni][0], s[ni][1]);
                *(__half2*)(Ph + (mw + qr + 8) * AH_LD + ni * 8 + qc * 2) =
                    __floats2half2_rn(s[ni][2], s[ni][3]);
            }
        }
        __syncwarp();

        // O += P V
        const uint32_t* Pw = smu + AHT_POFF;
        const uint32_t* Vw = smu + AHT_VOFF;
#pragma unroll
        for (int kk = 0; kk < 4; kk++) {
            uint32_t pa[4];
            const int base = (mw + qr) * AH_LDW + kk * 8 + qc;
            pa[0] = Pw[base];
            pa[1] = Pw[base + 8 * AH_LDW];
            pa[2] = Pw[base + 4];
            pa[3] = Pw[base + 8 * AH_LDW + 4];
#pragma unroll
            for (int ni = 0; ni < 8; ni++) {
                const int vb = (ni * 8 + qr) * AH_LDW + kk * 8 + qc;
                uint32_t bfr[2] = { Vw[vb], Vw[vb + 4] };
                mma_f16(o[ni], pa, bfr);
            }
        }
        __syncthreads();
    }

    // epilogue
    const float inv0 = 1.f / lrow[0];
    const float inv1 = 1.f / lrow[1];
    const int r0 = q0 + mw + qr;
    const int r1 = r0 + 8;
    __half* d0 = obuf + (size_t)(b * SEQ + r0) * DMODEL + hd * 64;
    __half* d1 = obuf + (size_t)(b * SEQ + r1) * DMODEL + hd * 64;
#pragma unroll
    for (int ni = 0; ni < 8; ni++) {
        const int nb = ni * 8 + qc * 2;
        *(__half2*)(d0 + nb) = __floats2half2_rn(o[ni][0] * inv0, o[ni][1] * inv0);
        *(__half2*)(d1 + nb) = __floats2half2_rn(o[ni][2] * inv1, o[ni][3] * inv1);
    }
}

// =================================================================================
// LayerNorm over D=1024; optional fp16 copy of the output
// =================================================================================
template<bool OUTH>
__global__ void __launch_bounds__(256) ln_kernel(
    const float* __restrict__ in, const float* __restrict__ g,
    const float* __restrict__ b, float* __restrict__ out, __half* __restrict__ outh)
{
    const int row = blockIdx.x;
    const int tid = threadIdx.x;
    const float4 v = ((const float4*)(in + (size_t)row * DMODEL))[tid];

    float s  = v.x + v.y + v.z + v.w;
    float sq = v.x * v.x + v.y * v.y + v.z * v.z + v.w * v.w;
#pragma unroll
    for (int off = 16; off > 0; off >>= 1) {
        s  += __shfl_xor_sync(0xffffffffu, s,  off);
        sq += __shfl_xor_sync(0xffffffffu, sq, off);
    }
    __shared__ float ss[8], ssq[8];
    if ((tid & 31) == 0) { ss[tid >> 5] = s; ssq[tid >> 5] = sq; }
    __syncthreads();
    s = 0.f; sq = 0.f;
#pragma unroll
    for (int i = 0; i < 8; i++) { s += ss[i]; sq += ssq[i]; }

    const float mu   = s * (1.f / DMODEL);
    const float var  = sq * (1.f / DMODEL) - mu * mu;
    const float rstd = rsqrtf(var + 1e-5f);

    const float4 gg = ((const float4*)g)[tid];
    const float4 bb = ((const float4*)b)[tid];
    float4 r;
    r.x = (v.x - mu) * rstd * gg.x + bb.x;
    r.y = (v.y - mu) * rstd * gg.y + bb.y;
    r.z = (v.z - mu) * rstd * gg.z + bb.z;
    r.w = (v.w - mu) * rstd * gg.w + bb.w;
    ((float4*)(out + (size_t)row * DMODEL))[tid] = r;
    if (OUTH) {
        __half* oh = outh + (size_t)row * DMODEL + tid * 4;
        *(__half2*)(oh)     = __floats2half2_rn(r.x, r.y);
        *(__half2*)(oh + 2) = __floats2half2_rn(r.z, r.w);
    }
}

// =================================================================================
// Host launcher
// =================================================================================
extern "C" void kernel_launch(void* const* d_in, const int* in_sizes, int n_in,
                              void* d_out, int out_size)
{
    (void)in_sizes; (void)n_in; (void)out_size;
    const float* x     = (const float*)d_in[0];
    const float* wq    = (const float*)d_in[1];
    const float* bq    = (const float*)d_in[2];
    const float* wk    = (const float*)d_in[3];
    const float* bk    = (const float*)d_in[4];
    const float* wv    = (const float*)d_in[5];
    const float* bv    = (const float*)d_in[6];
    const float* wo    = (const float*)d_in[7];
    const float* bo    = (const float*)d_in[8];
    const float* ln1_g = (const float*)d_in[9];
    const float* ln1_b = (const float*)d_in[10];
    const float* w1    = (const float*)d_in[11];
    const float* b1    = (const float*)d_in[12];
    const float* w2    = (const float*)d_in[13];
    const float* b2    = (const float*)d_in[14];
    const float* ln2_g = (const float*)d_in[15];
    const float* ln2_b = (const float*)d_in[16];
    float* out = (float*)d_out;

    static __half *p_qkv = nullptr, *p_attn = nullptr, *p_yh = nullptr, *p_ff = nullptr,
                  *p_xh = nullptr, *p_wqkvT = nullptr, *p_woT = nullptr, *p_w1T = nullptr,
                  *p_w2T = nullptr;
    static float *p_tmp = nullptr, *p_y = nullptr, *p_bqkv = nullptr;
    if (!p_qkv) {
        cudaGetSymbolAddress((void**)&p_qkv,   g_qkv);
        cudaGetSymbolAddress((void**)&p_attn,  g_attn);
        cudaGetSymbolAddress((void**)&p_tmp,   g_tmp);
        cudaGetSymbolAddress((void**)&p_y,     g_y);
        cudaGetSymbolAddress((void**)&p_yh,    g_yh);
        cudaGetSymbolAddress((void**)&p_ff,    g_ff);
        cudaGetSymbolAddress((void**)&p_xh,    g_xh);
        cudaGetSymbolAddress((void**)&p_wqkvT, g_wqkvT);
        cudaGetSymbolAddress((void**)&p_woT,   g_woT);
        cudaGetSymbolAddress((void**)&p_w1T,   g_w1T);
        cudaGetSymbolAddress((void**)&p_w2T,   g_w2T);
        cudaGetSymbolAddress((void**)&p_bqkv,  g_bqkv);
        cudaFuncSetAttribute(attn_mma_kernel,
                             cudaFuncAttributeMaxDynamicSharedMemorySize, ATT_SMEM_BYTES);
        cudaFuncSetAttribute(mma_gemm<false, false, true>,
                             cudaFuncAttributeMaxDynamicSharedMemorySize, GM_SMEM_BYTES);
        cudaFuncSetAttribute(mma_gemm<false, true, false>,
                             cudaFuncAttributeMaxDynamicSharedMemorySize, GM_SMEM_BYTES);
        cudaFuncSetAttribute(mma_gemm<true, false, true>,
                             cudaFuncAttributeMaxDynamicSharedMemorySize, GM_SMEM_BYTES);
    }

    // 0) producers: x->fp16, weight transposes (fp16), bias concat
    f2h_kernel<<<MTOK * DMODEL / 1024, 256>>>(x, p_xh);
    qkvw_transpose_kernel<<<dim3(2, 32, 48), dim3(32, 8)>>>(wq, wk, wv, p_wqkvT);
    transpose_kernel<<<dim3(32, 32),  dim3(32, 8)>>>(wo, p_woT, DMODEL, DMODEL);
    transpose_kernel<<<dim3(128, 32), dim3(32, 8)>>>(w1, p_w1T, DMODEL, FF);
    transpose_kernel<<<dim3(32, 128), dim3(32, 8)>>>(w2, p_w2T, FF, DMODEL);
    biascat_kernel<<<12, 256>>>(bq, bk, bv, p_bqkv);

    // 1) fused QKV projection -> fp16
    mma_gemm<false, false, true><<<dim3(MTOK / 128, QKVLD / 128), 128, GM_SMEM_BYTES>>>(
        p_xh, p_wqkvT, p_bqkv, nullptr, nullptr, p_qkv, MTOK, QKVLD, DMODEL);

    // 2) fused attention (fp16 mma) -> fp16
    attn_mma_kernel<<<dim3(SEQ / 128, NBATCH * NH), 256, ATT_SMEM_BYTES>>>(p_qkv, p_attn);

    // 3) output projection + bias + residual(x fp32) -> fp32
    mma_gemm<false, true, false><<<dim3(MTOK / 128, DMODEL / 128), 128, GM_SMEM_BYTES>>>(
        p_attn, p_woT, bo, x, p_tmp, nullptr, MTOK, DMODEL, DMODEL);

    // 4) LN1 -> y (fp32) + yh (fp16)
    ln_kernel<true><<<MTOK, 256>>>(p_tmp, ln1_g, ln1_b, p_y, p_yh);

    // 5) FFN1: relu(y*w1 + b1) -> fp16
    mma_gemm<true, false, true><<<dim3(MTOK / 128, FF / 128), 128, GM_SMEM_BYTES>>>(
        p_yh, p_w1T, b1, nullptr, nullptr, p_ff, MTOK, FF, DMODEL);

    // 6) FFN2: ff*w2 + b2 + residual(y fp32) -> fp32
    mma_gemm<false, true, false><<<dim3(MTOK / 128, DMODEL / 128), 128, GM_SMEM_BYTES>>>(
        p_ff, p_w2T, b2, p_y, p_tmp, nullptr, MTOK, DMODEL, FF);

    // 7) LN2 -> out
    ln_kernel<false><<<MTOK, 256>>>(p_tmp, ln2_g, ln2_b, out, nullptr);
}

// round 11
// speedup vs baseline: 6.6616x; 1.0325x over previous
#include <cuda_runtime.h>
#include <cuda_fp16.h>
#include <math.h>
#include <stdint.h>

#define SEQ     2048
#define DMODEL  1024
#define NH      16
#define DHEAD   64
#define FF      4096
#define MTOK    8192   // B*S
#define NBATCH  4
#define QKVLD   3072   // q|k|v concatenated row stride (halfs)

// ---------------- scratch (static device globals; no allocations) ----------------
__device__ __half g_qkv [(size_t)MTOK * QKVLD];
__device__ __half g_attn[(size_t)MTOK * DMODEL];
__device__ float  g_tmp [(size_t)MTOK * DMODEL];
__device__ float  g_y   [(size_t)MTOK * DMODEL];
__device__ __half g_yh  [(size_t)MTOK * DMODEL];
__device__ __half g_ff  [(size_t)MTOK * FF];
__device__ __half g_xh  [(size_t)MTOK * DMODEL];
__device__ __half g_wqkvT[(size_t)QKVLD * DMODEL];
__device__ __half g_woT [(size_t)DMODEL * DMODEL];
__device__ __half g_w1T [(size_t)FF * DMODEL];
__device__ __half g_w2T [(size_t)DMODEL * FF];
__device__ float  g_bqkv[QKVLD];

// ======================= helpers =======================
__device__ __forceinline__ uint32_t smem_u32(const void* p) {
    uint32_t a;
    asm("{ .reg .u64 t; cvta.to.shared.u64 t, %1; cvt.u32.u64 %0, t; }" : "=r"(a) : "l"(p));
    return a;
}
__device__ __forceinline__ void cp16(uint32_t dst, const void* src) {
    asm volatile("cp.async.cg.shared.global [%0], [%1], 16;" :: "r"(dst), "l"(src));
}
__device__ __forceinline__ void mma_f16(float* d, const uint32_t* a, const uint32_t* b) {
    asm volatile("mma.sync.aligned.m16n8k16.row.col.f32.f16.f16.f32 "
                 "{%0,%1,%2,%3}, {%4,%5,%6,%7}, {%8,%9}, {%0,%1,%2,%3};"
                 : "+f"(d[0]), "+f"(d[1]), "+f"(d[2]), "+f"(d[3])
                 : "r"(a[0]), "r"(a[1]), "r"(a[2]), "r"(a[3]), "r"(b[0]), "r"(b[1]));
}

// =================================================================================
// FP16 mma.sync GEMM: C[M,N] = A[M,K]*Bt[N,K]^T + bias (+resid fp32) (relu)
// CTA 128x128, BK=32, 128 threads, warp tile 64x64, 3-stage cp.async,
// ONE __syncthreads per chunk (prefetch issued after the barrier).
// =================================================================================
#define GH_LDH 40
#define GH_LDW 20
#define GH_STAGE_W (128 * GH_LDW)
#define GH_STAGES 3
#define GM_SMEM_BYTES (2 * GH_STAGES * GH_STAGE_W * 4)  // 61440

template<bool RELU, bool RESID, bool OUTH>
__global__ void __launch_bounds__(128, 2) mma_gemm(
    const __half* __restrict__ A, const __half* __restrict__ Bt,
    const float* __restrict__ bias, const float* __restrict__ resid,
    float* __restrict__ Cf, __half* __restrict__ Ch, int M, int N, int K)
{
    extern __shared__ __align__(16) uint32_t smw[];
    const uint32_t sb = smem_u32(smw);
    const int t    = threadIdx.x;
    const int lane = t & 31;
    const int w    = t >> 5;
    const int wm   = w & 1;
    const int wn   = w >> 1;
    const int qr   = lane >> 2;
    const int qc   = lane & 3;
    const int m0   = blockIdx.x * 128;
    const int n0   = blockIdx.y * 128;

    float acc[4][8][4];
#pragma unroll
    for (int mi = 0; mi < 4; mi++)
#pragma unroll
        for (int ni = 0; ni < 8; ni++)
#pragma unroll
            for (int k = 0; k < 4; k++) acc[mi][ni][k] = 0.f;

    const int NC = K >> 5;

    auto load_chunk = [&](int c, int s) {
        const int k0 = c << 5;
#pragma unroll
        for (int i = 0; i < 4; i++) {
            const int id = t + 128 * i;
            const int r = id >> 2, sg = id & 3;
            cp16(sb + 4u * (s * GH_STAGE_W + r * GH_LDW + sg * 4),
                 A + (size_t)(m0 + r) * K + k0 + sg * 8);
        }
#pragma unroll
        for (int i = 0; i < 4; i++) {
            const int id = t + 128 * i;
            const int r = id >> 2, sg = id & 3;
            cp16(sb + 4u * (GH_STAGES * GH_STAGE_W + s * GH_STAGE_W + r * GH_LDW + sg * 4),
                 Bt + (size_t)(n0 + r) * K + k0 + sg * 8);
        }
        asm volatile("cp.async.commit_group;" ::: "memory");
    };

    load_chunk(0, 0);
    load_chunk(1, 1);

    int scur = 0;
    for (int c = 0; c < NC; ++c) {
        if (c + 1 < NC)
            asm volatile("cp.async.wait_group 1;" ::: "memory");
        else
            asm volatile("cp.async.wait_group 0;" ::: "memory");
        __syncthreads();   // buf scur ready for all; all warps done with buf scur+2 (mod 3)

        if (c + 2 < NC) {
            int s2 = scur + 2; if (s2 >= GH_STAGES) s2 -= GH_STAGES;
            load_chunk(c + 2, s2);
        }

        const uint32_t* Aw = smw + scur * GH_STAGE_W;
        const uint32_t* Bw = smw + GH_STAGES * GH_STAGE_W + scur * GH_STAGE_W;

#pragma unroll
        for (int kk = 0; kk < 2; kk++) {
            uint32_t af[4][4], bf[8][2];
#pragma unroll
            for (int mi = 0; mi < 4; mi++) {
                const int base = (wm * 64 + mi * 16 + qr) * GH_LDW + kk * 8 + qc;
                af[mi][0] = Aw[base];
                af[mi][1] = Aw[base + 8 * GH_LDW];
                af[mi][2] = Aw[base + 4];
                af[mi][3] = Aw[base + 8 * GH_LDW + 4];
            }
#pragma unroll
            for (int ni = 0; ni < 8; ni++) {
                const int bbx = (wn * 64 + ni * 8 + qr) * GH_LDW + kk * 8 + qc;
                bf[ni][0] = Bw[bbx];
                bf[ni][1] = Bw[bbx + 4];
            }
#pragma unroll
            for (int mi = 0; mi < 4; mi++)
#pragma unroll
                for (int ni = 0; ni < 8; ni++)
                    mma_f16(acc[mi][ni], af[mi], bf[ni]);
        }
        if (++scur == GH_STAGES) scur = 0;
    }

    // epilogue
#pragma unroll
    for (int mi = 0; mi < 4; mi++) {
        const int r0 = m0 + wm * 64 + mi * 16 + qr;
        const int r1 = r0 + 8;
#pragma unroll
        for (int ni = 0; ni < 8; ni++) {
            const int nb = n0 + wn * 64 + ni * 8 + qc * 2;
            const float b0 = bias[nb], b1 = bias[nb + 1];
            float2 v0, v1;
            v0.x = acc[mi][ni][0] + b0; v0.y = acc[mi][ni][1] + b1;
            v1.x = acc[mi][ni][2] + b0; v1.y = acc[mi][ni][3] + b1;
            if (RESID) {
                const float2 q0 = *(const float2*)(resid + (size_t)r0 * N + nb);
                const float2 q1 = *(const float2*)(resid + (size_t)r1 * N + nb);
                v0.x += q0.x; v0.y += q0.y; v1.x += q1.x; v1.y += q1.y;
            }
            if (RELU) {
                v0.x = fmaxf(v0.x, 0.f); v0.y = fmaxf(v0.y, 0.f);
                v1.x = fmaxf(v1.x, 0.f); v1.y = fmaxf(v1.y, 0.f);
            }
            if (OUTH) {
                *(__half2*)(Ch + (size_t)r0 * N + nb) = __floats2half2_rn(v0.x, v0.y);
                *(__half2*)(Ch + (size_t)r1 * N + nb) = __floats2half2_rn(v1.x, v1.y);
            } else {
                *(float2*)(Cf + (size_t)r0 * N + nb) = v0;
                *(float2*)(Cf + (size_t)r1 * N + nb) = v1;
            }
        }
    }
}

// =================================================================================
// Combined prep: weight transposes (fp16), x->fp16, bias concat. One launch.
// Block ranges (256 threads each):
//   [0,1024)       wo   transpose tiles (32x32 grid)
//   [1024,5120)    w1   (128x32)
//   [5120,9216)    w2   (32x128)
//   [9216,12288)   wqkv (2x32x48)
//   [12288,20480)  x -> fp16 (1024 floats per block)
//   [20480,20492)  bias concat (256 per block)
// =================================================================================
__device__ __forceinline__ void tr32_tile(float (*tile)[33],
    const float* __restrict__ in, __half* __restrict__ out,
    int R, int C, int bx, int by, int tx, int ty)
{
    const int c0 = bx * 32, r0 = by * 32;
#pragma unroll
    for (int i = 0; i < 4; i++)
        tile[ty + 8 * i][tx] = in[(size_t)(r0 + ty + 8 * i) * C + c0 + tx];
    __syncthreads();
#pragma unroll
    for (int i = 0; i < 4; i++)
        out[(size_t)(c0 + ty + 8 * i) * R + r0 + tx] =
            __float2half_rn(tile[tx][ty + 8 * i]);
}

__global__ void __launch_bounds__(256) prep_kernel(
    const float* __restrict__ x,
    const float* __restrict__ wq, const float* __restrict__ wk, const float* __restrict__ wv,
    const float* __restrict__ bq, const float* __restrict__ bk, const float* __restrict__ bv,
    const float* __restrict__ wo, const float* __restrict__ w1, const float* __restrict__ w2,
    __half* __restrict__ xh, __half* __restrict__ wqkvT, __half* __restrict__ woT,
    __half* __restrict__ w1T, __half* __restrict__ w2T, float* __restrict__ bqkv)
{
    __shared__ float tile[32][33];
    const int bid = blockIdx.x;
    const int t = threadIdx.x, tx = t & 31, ty = t >> 5;

    if (bid < 1024) {
        tr32_tile(tile, wo, woT, DMODEL, DMODEL, bid & 31, bid >> 5, tx, ty);
    } else if (bid < 5120) {
        const int id = bid - 1024;
        tr32_tile(tile, w1, w1T, DMODEL, FF, id & 127, id >> 7, tx, ty);
    } else if (bid < 9216) {
        const int id = bid - 5120;
        tr32_tile(tile, w2, w2T, FF, DMODEL, id & 31, id >> 5, tx, ty);
    } else if (bid < 12288) {
        const int id = bid - 9216;
        const int z = id >> 6, rem = id & 63;
        const int zz = z / 16, h = z & 15;
        const float* src = (zz == 0 ? wq : (zz == 1 ? wk : wv)) + (size_t)h * DMODEL * DHEAD;
        __half* dst = wqkvT + ((size_t)(zz * 16 + h)) * DHEAD * DMODEL;
        tr32_tile(tile, src, dst, DMODEL, DHEAD, rem & 1, rem >> 1, tx, ty);
    } else if (bid < 20480) {
        const size_t i = ((size_t)(bid - 12288) * 256 + t) * 4;
        const float4 v = *(const float4*)(x + i);
        *(__half2*)(xh + i)     = __floats2half2_rn(v.x, v.y);
        *(__half2*)(xh + i + 2) = __floats2half2_rn(v.z, v.w);
    } else {
        const int i = (bid - 20480) * 256 + t;
        bqkv[i] = (i < 1024) ? bq[i] : ((i < 2048) ? bk[i - 1024] : bv[i - 2048]);
    }
}

// =================================================================================
// Fused flash attention, fp16 m16n8k16 mma.
// 256 threads / 8 warps, 128 q-rows per CTA; K and Vt double-buffered;
// ONE __syncthreads per KV tile.
// =================================================================================
#define AH_LD  72
#define AH_LDW 36
#define AHT_QOFF 0                        // 128*36 = 4608 words
#define AHT_KOFF 4608                     // 2 x 2304
#define AHT_VOFF (4608 + 4608)            // 2 x 2304
#define AHT_POFF (AHT_VOFF + 4608)        // 4608
#define AHT_WORDS (AHT_POFF + 4608)       // 18432 words
#define ATT_SMEM_BYTES (AHT_WORDS * 4)    // 73728

__global__ void __launch_bounds__(256, 2) attn_mma_kernel(
    const __half* __restrict__ qkv, __half* __restrict__ obuf)
{
    extern __shared__ __align__(16) uint32_t smu[];
    __half* smh = (__half*)smu;
    const uint32_t sb = smem_u32(smu);
    const int t = threadIdx.x, lane = t & 31, w = t >> 5;
    const int qr = lane >> 2, qc = lane & 3;
    const int mw = w * 16;
    const int bh = blockIdx.y;
    const int b = bh >> 4, hd = bh & 15;
    const int q0 = blockIdx.x * 128;

    // stage Q (scaled by 1/sqrt(64)*log2e) as fp16
    {
        const float sc = 0.125f * 1.4426950408889634f;
        const int row = t >> 1, hoff = (t & 1) * 32;
        const __half* Q = qkv + (size_t)(b * SEQ + q0 + row) * QKVLD + hd * 64 + hoff;
        __half* dst = smh + (size_t)row * AH_LD + hoff;
#pragma unroll
        for (int c = 0; c < 32; c += 2) {
            const float2 f = __half22float2(*(const __half2*)(Q + c));
            *(__half2*)(dst + c) = __floats2half2_rn(f.x * sc, f.y * sc);
        }
    }

    const __half* Kp = qkv + (size_t)b * SEQ * QKVLD + 1024 + hd * 64;
    const __half* Vp = qkv + (size_t)b * SEQ * QKVLD + 2048 + hd * 64;

    auto load_k = [&](int kt, int s) {
#pragma unroll
        for (int i = 0; i < 2; i++) {
            const int id = t + 256 * i;
            const int r = id >> 3, sg = id & 7;
            cp16(sb + 4u * (AHT_KOFF + s * 2304 + r * AH_LDW) + sg * 16,
                 Kp + (size_t)(kt * 64 + r) * QKVLD + sg * 8);
        }
        asm volatile("cp.async.commit_group;" ::: "memory");
    };

    const int vkv = t >> 2, vseg = (t & 3) * 16;
    float4 vr0, vr1;
    auto ldg_v = [&](int kt) {
        const float4* p = (const float4*)(Vp + (size_t)(kt * 64 + vkv) * QKVLD + vseg);
        vr0 = p[0]; vr1 = p[1];
    };

    load_k(0, 0);
    ldg_v(0);
    __syncthreads();   // Q staged

    // Q fragments -> registers (fixed all kernel)
    uint32_t qa[4][4];
    {
        const uint32_t* Qw = smu;
#pragma unroll
        for (int kk = 0; kk < 4; kk++) {
            const int base = (mw + qr) * AH_LDW + kk * 8 + qc;
            qa[kk][0] = Qw[base];
            qa[kk][1] = Qw[base + 8 * AH_LDW];
            qa[kk][2] = Qw[base + 4];
            qa[kk][3] = Qw[base + 8 * AH_LDW + 4];
        }
    }

    float o[8][4];
    float mrow[2] = { -INFINITY, -INFINITY };
    float lrow[2] = { 0.f, 0.f };
#pragma unroll
    for (int ni = 0; ni < 8; ni++)
#pragma unroll
        for (int k = 0; k < 4; k++) o[ni][k] = 0.f;

    const int NT = SEQ / 64;
    for (int kt = 0; kt < NT; kt++) {
        const int buf = kt & 1;

        // 1) store prefetched V regs -> Vt[buf] (transposed [e][kv])
        {
            __half* vt = smh + 2 * (AHT_VOFF + buf * 2304);
            const __half* h0 = (const __half*)&vr0;
            const __half* h1 = (const __half*)&vr1;
#pragma unroll
            for (int j = 0; j < 8; j++) vt[(vseg + j) * AH_LD + vkv] = h0[j];
#pragma unroll
            for (int j = 0; j < 8; j++) vt[(vseg + 8 + j) * AH_LD + vkv] = h1[j];
        }

        // 2) K[buf] arrived
        asm volatile("cp.async.wait_group 0;" ::: "memory");
        // 3) single barrier: Vt[buf]+K[buf] visible; everyone done with buf^1
        __syncthreads();
        // 4) prefetch next K (overlaps compute)
        if (kt + 1 < NT) load_k(kt + 1, 1 - buf);
        // 5) prefetch next V into regs
        ldg_v(kt + 1 < NT ? kt + 1 : NT - 1);

        const uint32_t* Kw = smu + AHT_KOFF + buf * 2304;

        // S = Q K^T
        float s[8][4];
#pragma unroll
        for (int ni = 0; ni < 8; ni++)
#pragma unroll
            for (int k = 0; k < 4; k++) s[ni][k] = 0.f;
#pragma unroll
        for (int kk = 0; kk < 4; kk++) {
#pragma unroll
            for (int ni = 0; ni < 8; ni++) {
                const int bbx = (ni * 8 + qr) * AH_LDW + kk * 8 + qc;
                uint32_t bfr[2] = { Kw[bbx], Kw[bbx + 4] };
                mma_f16(s[ni], qa[kk], bfr);
            }
        }

        // online softmax (base-2)
#pragma unroll
        for (int h2 = 0; h2 < 2; h2++) {
            float vm = -INFINITY;
#pragma unroll
            for (int ni = 0; ni < 8; ni++)
                vm = fmaxf(vm, fmaxf(s[ni][2 * h2], s[ni][2 * h2 + 1]));
            vm = fmaxf(vm, __shfl_xor_sync(0xffffffffu, vm, 1));
            vm = fmaxf(vm, __shfl_xor_sync(0xffffffffu, vm, 2));
            const float mn = fmaxf(mrow[h2], vm);
            const float alpha = exp2f(mrow[h2] - mn);
            mrow[h2] = mn;
            float rs = 0.f;
#pragma unroll
            for (int ni = 0; ni < 8; ni++) {
                const float p0 = exp2f(s[ni][2 * h2] - mn);
                const float p1 = exp2f(s[ni][2 * h2 + 1] - mn);
                s[ni][2 * h2] = p0; s[ni][2 * h2 + 1] = p1;
                rs += p0 + p1;
            }
            rs += __shfl_xor_sync(0xffffffffu, rs, 1);
            rs += __shfl_xor_sync(0xffffffffu, rs, 2);
            lrow[h2] = lrow[h2] * alpha + rs;
#pragma unroll
            for (int ni = 0; ni < 8; ni++) {
                o[ni][2 * h2]     *= alpha;
                o[ni][2 * h2 + 1] *= alpha;
            }
        }

        // P -> smem fp16 (warp-private rows)
        {
            __half* Ph = smh + 2 * AHT_POFF;
#pragma unroll
            for (int ni = 0; ni < 8; ni++) {
                *(__half2*)(Ph + (mw + qr) * AH_LD + ni * 8 + qc * 2) =
                    __floats2half2_rn(s[ni][0], s[ni][1]);
                *(__half2*)(Ph + (mw + qr + 8) * AH_LD + ni * 8 + qc * 2) =
                    __floats2half2_rn(s[ni][2], s[ni][3]);
            }
        }
        __syncwarp();

        // O += P V  (Vt[buf])
        const uint32_t* Pw = smu + AHT_POFF;
        const uint32_t* Vw = smu + AHT_VOFF + buf * 2304;
#pragma unroll
        for (int kk = 0; kk < 4; kk++) {
            uint32_t pa[4];
            const int base = (mw + qr) * AH_LDW + kk * 8 + qc;
            pa[0] = Pw[base];
            pa[1] = Pw[base + 8 * AH_LDW];
            pa[2] = Pw[base + 4];
            pa[3] = Pw[base + 8 * AH_LDW + 4];
#pragma unroll
            for (int ni = 0; ni < 8; ni++) {
                const int vb = (ni * 8 + qr) * AH_LDW + kk * 8 + qc;
                uint32_t bfr[2] = { Vw[vb], Vw[vb + 4] };
                mma_f16(o[ni], pa, bfr);
            }
        }
    }

    // epilogue
    const float inv0 = 1.f / lrow[0];
    const float inv1 = 1.f / lrow[1];
    const int r0 = q0 + mw + qr;
    const int r1 = r0 + 8;
    __half* d0 = obuf + (size_t)(b * SEQ + r0) * DMODEL + hd * 64;
    __half* d1 = obuf + (size_t)(b * SEQ + r1) * DMODEL + hd * 64;
#pragma unroll
    for (int ni = 0; ni < 8; ni++) {
        const int nb = ni * 8 + qc * 2;
        *(__half2*)(d0 + nb) = __floats2half2_rn(o[ni][0] * inv0, o[ni][1] * inv0);
        *(__half2*)(d1 + nb) = __floats2half2_rn(o[ni][2] * inv1, o[ni][3] * inv1);
    }
}

// =================================================================================
// LayerNorm over D=1024; optional fp16 copy
// =================================================================================
template<bool OUTH>
__global__ void __launch_bounds__(256) ln_kernel(
    const float* __restrict__ in, const float* __restrict__ g,
    const float* __restrict__ b, float* __restrict__ out, __half* __restrict__ outh)
{
    const int row = blockIdx.x;
    const int tid = threadIdx.x;
    const float4 v = ((const float4*)(in + (size_t)row * DMODEL))[tid];

    float s  = v.x + v.y + v.z + v.w;
    float sq = v.x * v.x + v.y * v.y + v.z * v.z + v.w * v.w;
#pragma unroll
    for (int off = 16; off > 0; off >>= 1) {
        s  += __shfl_xor_sync(0xffffffffu, s,  off);
        sq += __shfl_xor_sync(0xffffffffu, sq, off);
    }
    __shared__ float ss[8], ssq[8];
    if ((tid & 31) == 0) { ss[tid >> 5] = s; ssq[tid >> 5] = sq; }
    __syncthreads();
    s = 0.f; sq = 0.f;
#pragma unroll
    for (int i = 0; i < 8; i++) { s += ss[i]; sq += ssq[i]; }

    const float mu   = s * (1.f / DMODEL);
    const float var  = sq * (1.f / DMODEL) - mu * mu;
    const float rstd = rsqrtf(var + 1e-5f);

    const float4 gg = ((const float4*)g)[tid];
    const float4 bb = ((const float4*)b)[tid];
    float4 r;
    r.x = (v.x - mu) * rstd * gg.x + bb.x;
    r.y = (v.y - mu) * rstd * gg.y + bb.y;
    r.z = (v.z - mu) * rstd * gg.z + bb.z;
    r.w = (v.w - mu) * rstd * gg.w + bb.w;
    ((float4*)(out + (size_t)row * DMODEL))[tid] = r;
    if (OUTH) {
        __half* oh = outh + (size_t)row * DMODEL + tid * 4;
        *(__half2*)(oh)     = __floats2half2_rn(r.x, r.y);
        *(__half2*)(oh + 2) = __floats2half2_rn(r.z, r.w);
    }
}

// =================================================================================
// Host launcher
// =================================================================================
extern "C" void kernel_launch(void* const* d_in, const int* in_sizes, int n_in,
                              void* d_out, int out_size)
{
    (void)in_sizes; (void)n_in; (void)out_size;
    const float* x     = (const float*)d_in[0];
    const float* wq    = (const float*)d_in[1];
    const float* bq    = (const float*)d_in[2];
    const float* wk    = (const float*)d_in[3];
    const float* bk    = (const float*)d_in[4];
    const float* wv    = (const float*)d_in[5];
    const float* bv    = (const float*)d_in[6];
    const float* wo    = (const float*)d_in[7];
    const float* bo    = (const float*)d_in[8];
    const float* ln1_g = (const float*)d_in[9];
    const float* ln1_b = (const float*)d_in[10];
    const float* w1    = (const float*)d_in[11];
    const float* b1    = (const float*)d_in[12];
    const float* w2    = (const float*)d_in[13];
    const float* b2    = (const float*)d_in[14];
    const float* ln2_g = (const float*)d_in[15];
    const float* ln2_b = (const float*)d_in[16];
    float* out = (float*)d_out;

    static __half *p_qkv = nullptr, *p_attn = nullptr, *p_yh = nullptr, *p_ff = nullptr,
                  *p_xh = nullptr, *p_wqkvT = nullptr, *p_woT = nullptr, *p_w1T = nullptr,
                  *p_w2T = nullptr;
    static float *p_tmp = nullptr, *p_y = nullptr, *p_bqkv = nullptr;
    if (!p_qkv) {
        cudaGetSymbolAddress((void**)&p_qkv,   g_qkv);
        cudaGetSymbolAddress((void**)&p_attn,  g_attn);
        cudaGetSymbolAddress((void**)&p_tmp,   g_tmp);
        cudaGetSymbolAddress((void**)&p_y,     g_y);
        cudaGetSymbolAddress((void**)&p_yh,    g_yh);
        cudaGetSymbolAddress((void**)&p_ff,    g_ff);
        cudaGetSymbolAddress((void**)&p_xh,    g_xh);
        cudaGetSymbolAddress((void**)&p_wqkvT, g_wqkvT);
        cudaGetSymbolAddress((void**)&p_woT,   g_woT);
        cudaGetSymbolAddress((void**)&p_w1T,   g_w1T);
        cudaGetSymbolAddress((void**)&p_w2T,   g_w2T);
        cudaGetSymbolAddress((void**)&p_bqkv,  g_bqkv);
        cudaFuncSetAttribute(attn_mma_kernel,
                             cudaFuncAttributeMaxDynamicSharedMemorySize, ATT_SMEM_BYTES);
        cudaFuncSetAttribute(mma_gemm<false, false, true>,
                             cudaFuncAttributeMaxDynamicSharedMemorySize, GM_SMEM_BYTES);
        cudaFuncSetAttribute(mma_gemm<false, true, false>,
                             cudaFuncAttributeMaxDynamicSharedMemorySize, GM_SMEM_BYTES);
        cudaFuncSetAttribute(mma_gemm<true, false, true>,
                             cudaFuncAttributeMaxDynamicSharedMemorySize, GM_SMEM_BYTES);
    }

    // 0) one combined prep launch
    prep_kernel<<<20492, 256>>>(x, wq, wk, wv, bq, bk, bv, wo, w1, w2,
                                p_xh, p_wqkvT, p_woT, p_w1T, p_w2T, p_bqkv);

    // 1) fused QKV projection -> fp16
    mma_gemm<false, false, true><<<dim3(MTOK / 128, QKVLD / 128), 128, GM_SMEM_BYTES>>>(
        p_xh, p_wqkvT, p_bqkv, nullptr, nullptr, p_qkv, MTOK, QKVLD, DMODEL);

    // 2) fused attention (fp16 mma) -> fp16
    attn_mma_kernel<<<dim3(SEQ / 128, NBATCH * NH), 256, ATT_SMEM_BYTES>>>(p_qkv, p_attn);

    // 3) output projection + bias + residual(x fp32) -> fp32
    mma_gemm<false, true, false><<<dim3(MTOK / 128, DMODEL / 128), 128, GM_SMEM_BYTES>>>(
        p_attn, p_woT, bo, x, p_tmp, nullptr, MTOK, DMODEL, DMODEL);

    // 4) LN1 -> y (fp32) + yh (fp16)
    ln_kernel<true><<<MTOK, 256>>>(p_tmp, ln1_g, ln1_b, p_y, p_yh);

    // 5) FFN1: relu(y*w1 + b1) -> fp16
    mma_gemm<true, false, true><<<dim3(MTOK / 128, FF / 128), 128, GM_SMEM_BYTES>>>(
        p_yh, p_w1T, b1, nullptr, nullptr, p_ff, MTOK, FF, DMODEL);

    // 6) FFN2: ff*w2 + b2 + residual(y fp32) -> fp32
    mma_gemm<false, true, false><<<dim3(MTOK / 128, DMODEL / 128), 128, GM_SMEM_BYTES>>>(
        p_ff, p_w2T, b2, p_y, p_tmp, nullptr, MTOK, DMODEL, FF);

    // 7) LN2 -> out
    ln_kernel<false><<<MTOK, 256>>>(p_tmp, ln2_g, ln2_b, out, nullptr);
}